// round 13
// baseline (speedup 1.0000x reference)
#include <cuda_runtime.h>
#include <cuda_bf16.h>
#include <math.h>
#include <stdint.h>

#define BSZ 4
#define SEQ 2048
#define EMB 1024
#define NH 16
#define HD 64
#define FFD 4096
#define MTOK 8192   // BSZ*SEQ
#define QKVN 3072   // fused q|k|v output width

// ---------------- scratch (static device arrays, allocation-free) ----------
__device__ __nv_bfloat16 s_qkvh[MTOK*QKVN], s_qkvl[MTOK*QKVN];  // fused QKV out
__device__ __nv_bfloat16 s_hh[MTOK*EMB], s_hl[MTOK*EMB];   // LN out hi/lo
__device__ __nv_bfloat16 s_yh[MTOK*EMB], s_yl[MTOK*EMB];   // attn out hi/lo
__device__ __nv_bfloat16 s_fh[MTOK*FFD], s_fl[MTOK*FFD];   // gelu out hi/lo
// transposed weights [N,K] hi/lo
__device__ __nv_bfloat16 w_qkvh[QKVN*EMB], w_qkvl[QKVN*EMB];   // q|k|v stacked
__device__ __nv_bfloat16 w_oh[EMB*EMB], w_ol[EMB*EMB];
__device__ __nv_bfloat16 w_1h[FFD*EMB], w_1l[FFD*EMB];
__device__ __nv_bfloat16 w_2h[EMB*FFD], w_2l[EMB*FFD];

// --------------------------- PTX helpers ------------------------------------
__device__ __forceinline__ uint32_t smem_u32(const void* p) {
    return (uint32_t)__cvta_generic_to_shared(p);
}
__device__ __forceinline__ void cp16(uint32_t dst, const void* src) {
    asm volatile("cp.async.ca.shared.global [%0], [%1], 16;" :: "r"(dst), "l"(src));
}
#define CP_COMMIT() asm volatile("cp.async.commit_group;" ::: "memory")
#define CP_WAIT1()  asm volatile("cp.async.wait_group 1;" ::: "memory")
#define CP_WAIT0()  asm volatile("cp.async.wait_group 0;" ::: "memory")

__device__ __forceinline__ void ldsm4(uint32_t* r, uint32_t addr) {
    asm volatile("ldmatrix.sync.aligned.m8n8.x4.shared.b16 {%0,%1,%2,%3}, [%4];"
        : "=r"(r[0]), "=r"(r[1]), "=r"(r[2]), "=r"(r[3]) : "r"(addr));
}
__device__ __forceinline__ void ldsm4t(uint32_t* r, uint32_t addr) {
    asm volatile("ldmatrix.sync.aligned.m8n8.x4.trans.shared.b16 {%0,%1,%2,%3}, [%4];"
        : "=r"(r[0]), "=r"(r[1]), "=r"(r[2]), "=r"(r[3]) : "r"(addr));
}
__device__ __forceinline__ void mma_bf16(float* d, const uint32_t* a, const uint32_t* b) {
    asm volatile("mma.sync.aligned.m16n8k16.row.col.f32.bf16.bf16.f32 "
        "{%0,%1,%2,%3}, {%4,%5,%6,%7}, {%8,%9}, {%0,%1,%2,%3};"
        : "+f"(d[0]), "+f"(d[1]), "+f"(d[2]), "+f"(d[3])
        : "r"(a[0]), "r"(a[1]), "r"(a[2]), "r"(a[3]), "r"(b[0]), "r"(b[1]));
}
// split two fp32 into packed bf16x2 hi and lo
__device__ __forceinline__ void split2(float x, float y, uint32_t& hi, uint32_t& lo) {
    __nv_bfloat16 hx = __float2bfloat16(x), hy = __float2bfloat16(y);
    __nv_bfloat162 H(hx, hy);
    __nv_bfloat162 L(__float2bfloat16(x - __bfloat162float(hx)),
                     __float2bfloat16(y - __bfloat162float(hy)));
    hi = *(uint32_t*)&H; lo = *(uint32_t*)&L;
}

// ---------------- weight prepass (batched): transpose + split ----------------
__device__ __forceinline__ void wprep_tile(
    const float* __restrict__ W, __nv_bfloat16* __restrict__ Th,
    __nv_bfloat16* __restrict__ Tl, int K, int N, int n0, int k0,
    int tx, int ty, float (*t)[33])
{
    #pragma unroll
    for (int j = 0; j < 4; j++)
        t[ty + 8*j][tx] = W[(size_t)(k0 + ty + 8*j) * N + n0 + tx];
    __syncthreads();
    #pragma unroll
    for (int j = 0; j < 4; j++) {
        int n = n0 + ty + 8*j, k = k0 + tx;
        float v = t[tx][ty + 8*j];
        __nv_bfloat16 h = __float2bfloat16(v);
        Th[(size_t)n * K + k] = h;
        Tl[(size_t)n * K + k] = __float2bfloat16(v - __bfloat162float(h));
    }
}

// batch 1: Wq, Wk, Wv (stacked into w_qkv), Wo.  grid (32, 32, 4), block (32,8)
__global__ void wprep_attn(
    const float* __restrict__ Wq, const float* __restrict__ Wk,
    const float* __restrict__ Wv, const float* __restrict__ Wo,
    __nv_bfloat16* __restrict__ qkvh, __nv_bfloat16* __restrict__ qkvl,
    __nv_bfloat16* __restrict__ oh, __nv_bfloat16* __restrict__ ol)
{
    __shared__ float t[32][33];
    int z = blockIdx.z;
    const float* W = (z == 0) ? Wq : (z == 1) ? Wk : (z == 2) ? Wv : Wo;
    __nv_bfloat16* Th = (z == 3) ? oh : qkvh + (size_t)z * EMB * EMB;
    __nv_bfloat16* Tl = (z == 3) ? ol : qkvl + (size_t)z * EMB * EMB;
    wprep_tile(W, Th, Tl, EMB, EMB, blockIdx.x * 32, blockIdx.y * 32,
               threadIdx.x, threadIdx.y, t);
}

// batch 2: W1 (K=EMB,N=FFD), W2 (K=FFD,N=EMB). grid (128, 128, 2), guarded.
__global__ void wprep_mlp(
    const float* __restrict__ W1, const float* __restrict__ W2,
    __nv_bfloat16* __restrict__ w1h, __nv_bfloat16* __restrict__ w1l,
    __nv_bfloat16* __restrict__ w2h, __nv_bfloat16* __restrict__ w2l)
{
    __shared__ float t[32][33];
    int z = blockIdx.z;
    const float* W = z ? W2 : W1;
    __nv_bfloat16* Th = z ? w2h : w1h;
    __nv_bfloat16* Tl = z ? w2l : w1l;
    int K = z ? FFD : EMB, N = z ? EMB : FFD;
    int n0 = blockIdx.x * 32, k0 = blockIdx.y * 32;
    if (n0 >= N || k0 >= K) return;
    wprep_tile(W, Th, Tl, K, N, n0, k0, threadIdx.x, threadIdx.y, t);
}

// ---------------------------- LayerNorm (bf16 hi/lo out) --------------------
__global__ __launch_bounds__(256) void ln_kernel(
    const float* __restrict__ x, const float* __restrict__ g,
    const float* __restrict__ bta, __nv_bfloat16* __restrict__ oh,
    __nv_bfloat16* __restrict__ ol)
{
    int row = blockIdx.x;
    int t = threadIdx.x;
    const float4* xr = (const float4*)(x + (size_t)row * EMB);
    float4 v = xr[t];
    float s  = v.x + v.y + v.z + v.w;
    float ss = v.x*v.x + v.y*v.y + v.z*v.z + v.w*v.w;
    #pragma unroll
    for (int o = 16; o; o >>= 1) {
        s  += __shfl_xor_sync(0xFFFFFFFFu, s,  o);
        ss += __shfl_xor_sync(0xFFFFFFFFu, ss, o);
    }
    __shared__ float sh_s[8], sh_ss[8];
    __shared__ float s_mu, s_rstd;
    int w = t >> 5;
    if ((t & 31) == 0) { sh_s[w] = s; sh_ss[w] = ss; }
    __syncthreads();
    if (t == 0) {
        float S = 0.f, SS = 0.f;
        #pragma unroll
        for (int i = 0; i < 8; i++) { S += sh_s[i]; SS += sh_ss[i]; }
        float mu  = S * (1.0f / EMB);
        float var = SS * (1.0f / EMB) - mu * mu;
        s_mu = mu; s_rstd = rsqrtf(var + 1e-5f);
    }
    __syncthreads();
    float mu = s_mu, rs = s_rstd;
    float4 gv = ((const float4*)g)[t];
    float4 bv = ((const float4*)bta)[t];
    float o[4];
    o[0] = (v.x - mu) * rs * gv.x + bv.x;
    o[1] = (v.y - mu) * rs * gv.y + bv.y;
    o[2] = (v.z - mu) * rs * gv.z + bv.z;
    o[3] = (v.w - mu) * rs * gv.w + bv.w;
    size_t base = (size_t)row * EMB + t * 4;
    #pragma unroll
    for (int i = 0; i < 4; i++) {
        __nv_bfloat16 h = __float2bfloat16(o[i]);
        oh[base + i] = h;
        ol[base + i] = __float2bfloat16(o[i] - __bfloat162float(h));
    }
}

// ----------------------- mma.sync GEMM (bf16x3 split) ------------------------
// mode 0: C = D+bias   mode 2: C = D+bias+resid
// mode 1: gelu(D+bias) -> (Oh,Ol)    mode 3: D+bias -> (Oh,Ol)
// bias2/bias3: optional per-1024-column-segment biases (fused QKV)
#define RSTRIDE 80
#define MAT_BYTES (128 * RSTRIDE)
#define STAGE_BYTES (4 * MAT_BYTES)
#define SMEM_TOTAL (2 * STAGE_BYTES)

__global__ __launch_bounds__(256) void gemm_mma(
    const __nv_bfloat16* __restrict__ Ah, const __nv_bfloat16* __restrict__ Al,
    const __nv_bfloat16* __restrict__ Bh, const __nv_bfloat16* __restrict__ Bl,
    const float* __restrict__ bias, const float* __restrict__ bias2,
    const float* __restrict__ bias3, const float* __restrict__ resid,
    float* __restrict__ C, __nv_bfloat16* __restrict__ Oh,
    __nv_bfloat16* __restrict__ Ol, int M, int N, int K, int mode)
{
    extern __shared__ char smem[];
    const uint32_t sb = smem_u32(smem);
    const int tid = threadIdx.x;
    const int lane = tid & 31, warp = tid >> 5;
    const int wm = warp & 1, wn = warp >> 1;
    const int bn = blockIdx.x * 128, bm = blockIdx.y * 128;
    const int nch = K >> 5;

    const char* gp[8];
    uint32_t sdst[8];
    #pragma unroll
    for (int i = 0; i < 8; i++) {
        int f = tid + i * 256;
        int mat = f >> 9;
        int row = (f >> 2) & 127;
        int ch  = f & 3;
        const __nv_bfloat16* base =
            (mat == 0) ? Ah : (mat == 1) ? Al : (mat == 2) ? Bh : Bl;
        int grow = (mat < 2) ? (bm + row) : (bn + row);
        gp[i] = (const char*)(base + (size_t)grow * K + ch * 8);
        sdst[i] = sb + mat * MAT_BYTES + row * RSTRIDE + ch * 16;
    }

    float acc[4][4][4];
    #pragma unroll
    for (int i = 0; i < 4; i++)
        #pragma unroll
        for (int j = 0; j < 4; j++)
            #pragma unroll
            for (int e = 0; e < 4; e++) acc[i][j][e] = 0.f;

    #pragma unroll
    for (int i = 0; i < 8; i++) { cp16(sdst[i], gp[i]); gp[i] += 64; }
    CP_COMMIT();

    const int g = lane >> 3, r = lane & 7;
    const uint32_t a_lane = (uint32_t)((wm * 64 + (g & 1) * 8 + r) * RSTRIDE + (g >> 1) * 16);
    const uint32_t b_lane = (uint32_t)((wn * 32 + (g >> 1) * 8 + r) * RSTRIDE + (g & 1) * 16);

    for (int c = 0; c < nch; c++) {
        const int s = c & 1;
        if (c + 1 < nch) {
            const uint32_t so = ((c + 1) & 1) * STAGE_BYTES;
            #pragma unroll
            for (int i = 0; i < 8; i++) { cp16(sdst[i] + so, gp[i]); gp[i] += 64; }
            CP_COMMIT();
            CP_WAIT1();
        } else {
            CP_WAIT0();
        }
        __syncthreads();

        const uint32_t st = sb + s * STAGE_BYTES;
        #pragma unroll
        for (int kk = 0; kk < 2; kk++) {
            uint32_t bh[2][4], bl[2][4];
            #pragma unroll
            for (int j = 0; j < 2; j++) {
                uint32_t baddr = st + b_lane + j * (16 * RSTRIDE) + kk * 32;
                ldsm4(bh[j], baddr + 2 * MAT_BYTES);
                ldsm4(bl[j], baddr + 3 * MAT_BYTES);
            }
            #pragma unroll
            for (int i = 0; i < 4; i++) {
                uint32_t ah[4], al[4];
                uint32_t aaddr = st + a_lane + i * (16 * RSTRIDE) + kk * 32;
                ldsm4(ah, aaddr);
                ldsm4(al, aaddr + MAT_BYTES);
                #pragma unroll
                for (int jj = 0; jj < 4; jj++) {
                    const uint32_t* Bh2 = &bh[jj >> 1][(jj & 1) * 2];
                    const uint32_t* Bl2 = &bl[jj >> 1][(jj & 1) * 2];
                    mma_bf16(acc[i][jj], ah, Bh2);
                    mma_bf16(acc[i][jj], ah, Bl2);
                    mma_bf16(acc[i][jj], al, Bh2);
                }
            }
        }
        __syncthreads();
    }

    // per-segment bias select (fused QKV): each 128-col CTA tile sits in one segment
    const float* bptr = bias;
    if (bias2) {
        int seg = bn >> 10;
        if (seg == 1) bptr = bias2 - 1024;
        else if (seg == 2) bptr = bias3 - 2048;
    }

    const int rb = bm + wm * 64 + (lane >> 2);
    const int cb = bn + wn * 32 + 2 * (lane & 3);
    #pragma unroll
    for (int i = 0; i < 4; i++) {
        #pragma unroll
        for (int j = 0; j < 4; j++) {
            int row0 = rb + i * 16;
            int col  = cb + j * 8;
            float b0 = __ldg(&bptr[col]), b1 = __ldg(&bptr[col + 1]);
            float v00 = acc[i][j][0] + b0, v01 = acc[i][j][1] + b1;
            float v10 = acc[i][j][2] + b0, v11 = acc[i][j][3] + b1;
            size_t i0 = (size_t)row0 * N + col;
            size_t i1 = (size_t)(row0 + 8) * N + col;
            if (mode == 1 || mode == 3) {
                if (mode == 1) {
                    v00 = 0.5f * v00 * (1.0f + erff(v00 * 0.70710678118654752f));
                    v01 = 0.5f * v01 * (1.0f + erff(v01 * 0.70710678118654752f));
                    v10 = 0.5f * v10 * (1.0f + erff(v10 * 0.70710678118654752f));
                    v11 = 0.5f * v11 * (1.0f + erff(v11 * 0.70710678118654752f));
                }
                uint32_t h0, l0, h1, l1;
                split2(v00, v01, h0, l0);
                split2(v10, v11, h1, l1);
                *(uint32_t*)(Oh + i0) = h0;
                *(uint32_t*)(Oh + i1) = h1;
                *(uint32_t*)(Ol + i0) = l0;
                *(uint32_t*)(Ol + i1) = l1;
            } else {
                if (mode == 2) {
                    float2 r0 = *(const float2*)(resid + i0);
                    float2 r1 = *(const float2*)(resid + i1);
                    v00 += r0.x; v01 += r0.y; v10 += r1.x; v11 += r1.y;
                }
                *(float2*)(C + i0) = make_float2(v00, v01);
                *(float2*)(C + i1) = make_float2(v10, v11);
            }
        }
    }
}

// ----------------- tensor-core flash attention (bf16x3 split) ---------------
// CTA: 128 q-rows, 8 warps (each m16), 64-key tiles, 2-stage cp.async.
// Q/K/V read from fused QKV buffer (row stride QKVN).
#define AT_RS 144
#define AQ_MAT (128 * AT_RS)            // 18432
#define AK_MAT (64 * AT_RS)             // 9216
#define AT_QB (2 * AQ_MAT)              // 36864
#define AT_ST (4 * AK_MAT)              // 36864
#define AT_SMEM (AT_QB + 2 * AT_ST)     // 110592

__global__ __launch_bounds__(256, 2) void attn_mma(
    const __nv_bfloat16* __restrict__ QKVh, const __nv_bfloat16* __restrict__ QKVl,
    __nv_bfloat16* __restrict__ Yh, __nv_bfloat16* __restrict__ Yl)
{
    extern __shared__ char sm[];
    const uint32_t sb = smem_u32(sm);
    const int qt = gridDim.x - 1 - blockIdx.x;          // heavy tiles first
    const int bh = blockIdx.y;
    const int b = bh >> 4, h = bh & 15;
    const int tid = threadIdx.x, lane = tid & 31, warp = tid >> 5;
    const size_t hoff = (size_t)h * HD;
    const int qtok = b * SEQ + qt * 128;

    const int rq = tid >> 3;                    // 0..31
    const int chb = (tid & 7) * 16;             // smem byte offset
    const size_t choff = (size_t)(tid & 7) * 8; // gmem dim offset

    const __nv_bfloat16* kv[4] = { QKVh + 1024, QKVl + 1024, QKVh + 2048, QKVl + 2048 };

    // ---- Q staging: 128 rows hi/lo ----
    #pragma unroll
    for (int mat = 0; mat < 2; mat++) {
        const __nv_bfloat16* base = mat ? QKVl : QKVh;
        #pragma unroll
        for (int rr = 0; rr < 4; rr++) {
            int row = rq + rr * 32;
            cp16(sb + mat * AQ_MAT + row * AT_RS + chb,
                 base + (size_t)(qtok + row) * QKVN + hoff + choff);
        }
    }
    CP_COMMIT();

    // ---- K/V tile 0 ----
    #pragma unroll
    for (int m = 0; m < 4; m++)
        #pragma unroll
        for (int rr = 0; rr < 2; rr++) {
            int row = rq + rr * 32;
            cp16(sb + AT_QB + m * AK_MAT + row * AT_RS + chb,
                 kv[m] + (size_t)(b * SEQ + row) * QKVN + hoff + choff);
        }
    CP_COMMIT();
    CP_WAIT1();
    __syncthreads();

    // ---- Q fragments (warp rows warp*16..+15) ----
    const int g = lane >> 3, rr8 = lane & 7;
    const uint32_t qlane = (uint32_t)((warp * 16 + (g & 1) * 8 + rr8) * AT_RS + (g >> 1) * 16);
    uint32_t qfh[4][4], qfl[4][4];
    #pragma unroll
    for (int ks = 0; ks < 4; ks++) {
        ldsm4(qfh[ks], sb + qlane + ks * 32);
        ldsm4(qfl[ks], sb + AQ_MAT + qlane + ks * 32);
    }

    const uint32_t klane = (uint32_t)(((g >> 1) * 8 + rr8) * AT_RS + (g & 1) * 16);
    const int vrow = (g & 1) * 8 + rr8;
    const uint32_t vcol = (uint32_t)((g >> 1) * 16);

    float o[8][4];
    #pragma unroll
    for (int t = 0; t < 8; t++)
        #pragma unroll
        for (int e = 0; e < 4; e++) o[t][e] = 0.f;
    float m0 = -INFINITY, m1 = -INFINITY, l0 = 0.f, l1 = 0.f;
    const int rg0 = qt * 128 + warp * 16 + (lane >> 2);
    const int cmax = 2 * qt + 1;

    for (int c = 0; c <= cmax; c++) {
        if (c < cmax) {
            const uint32_t so = sb + AT_QB + ((c + 1) & 1) * AT_ST;
            const int nt = b * SEQ + (c + 1) * 64;
            #pragma unroll
            for (int m = 0; m < 4; m++)
                #pragma unroll
                for (int rr = 0; rr < 2; rr++) {
                    int row = rq + rr * 32;
                    cp16(so + m * AK_MAT + row * AT_RS + chb,
                         kv[m] + (size_t)(nt + row) * QKVN + hoff + choff);
                }
            CP_COMMIT();
            CP_WAIT1();
        } else {
            CP_WAIT0();
        }
        __syncthreads();
        const uint32_t st = sb + AT_QB + (c & 1) * AT_ST;

        // ---- S = Q K^T ----
        float sc[8][4];
        #pragma unroll
        for (int t = 0; t < 8; t++)
            #pragma unroll
            for (int e = 0; e < 4; e++) sc[t][e] = 0.f;
        #pragma unroll
        for (int kk = 0; kk < 4; kk++) {
            #pragma unroll
            for (int j = 0; j < 4; j++) {
                uint32_t addr = st + klane + j * (16 * AT_RS) + kk * 32;
                uint32_t kh4[4], kl4[4];
                ldsm4(kh4, addr);
                ldsm4(kl4, addr + AK_MAT);
                #pragma unroll
                for (int jj = 0; jj < 2; jj++) {
                    int t = j * 2 + jj;
                    mma_bf16(sc[t], qfh[kk], &kh4[jj * 2]);
                    mma_bf16(sc[t], qfh[kk], &kl4[jj * 2]);
                    mma_bf16(sc[t], qfl[kk], &kh4[jj * 2]);
                }
            }
        }

        // ---- scale + causal mask (needed only once tile crosses diagonal) ----
        if (c >= 2 * qt) {
            #pragma unroll
            for (int t = 0; t < 8; t++) {
                int col = c * 64 + t * 8 + (lane & 3) * 2;
                sc[t][0] = (col     <= rg0)     ? sc[t][0] * 0.125f : -1e30f;
                sc[t][1] = (col + 1 <= rg0)     ? sc[t][1] * 0.125f : -1e30f;
                sc[t][2] = (col     <= rg0 + 8) ? sc[t][2] * 0.125f : -1e30f;
                sc[t][3] = (col + 1 <= rg0 + 8) ? sc[t][3] * 0.125f : -1e30f;
            }
        } else {
            #pragma unroll
            for (int t = 0; t < 8; t++)
                #pragma unroll
                for (int e = 0; e < 4; e++) sc[t][e] *= 0.125f;
        }

        // ---- online softmax ----
        float rx0 = -INFINITY, rx1 = -INFINITY;
        #pragma unroll
        for (int t = 0; t < 8; t++) {
            rx0 = fmaxf(rx0, fmaxf(sc[t][0], sc[t][1]));
            rx1 = fmaxf(rx1, fmaxf(sc[t][2], sc[t][3]));
        }
        rx0 = fmaxf(rx0, __shfl_xor_sync(0xFFFFFFFFu, rx0, 1));
        rx0 = fmaxf(rx0, __shfl_xor_sync(0xFFFFFFFFu, rx0, 2));
        rx1 = fmaxf(rx1, __shfl_xor_sync(0xFFFFFFFFu, rx1, 1));
        rx1 = fmaxf(rx1, __shfl_xor_sync(0xFFFFFFFFu, rx1, 2));
        float mn0 = fmaxf(m0, rx0), mn1 = fmaxf(m1, rx1);
        float cr0 = __expf(m0 - mn0), cr1 = __expf(m1 - mn1);
        m0 = mn0; m1 = mn1;
        float s0 = 0.f, s1 = 0.f;
        #pragma unroll
        for (int t = 0; t < 8; t++) {
            sc[t][0] = __expf(sc[t][0] - mn0); s0 += sc[t][0];
            sc[t][1] = __expf(sc[t][1] - mn0); s0 += sc[t][1];
            sc[t][2] = __expf(sc[t][2] - mn1); s1 += sc[t][2];
            sc[t][3] = __expf(sc[t][3] - mn1); s1 += sc[t][3];
        }
        s0 += __shfl_xor_sync(0xFFFFFFFFu, s0, 1);
        s0 += __shfl_xor_sync(0xFFFFFFFFu, s0, 2);
        s1 += __shfl_xor_sync(0xFFFFFFFFu, s1, 1);
        s1 += __shfl_xor_sync(0xFFFFFFFFu, s1, 2);
        l0 = l0 * cr0 + s0;
        l1 = l1 * cr1 + s1;
        #pragma unroll
        for (int t = 0; t < 8; t++) {
            o[t][0] *= cr0; o[t][1] *= cr0; o[t][2] *= cr1; o[t][3] *= cr1;
        }

        // ---- O += P V ----
        #pragma unroll
        for (int ks = 0; ks < 4; ks++) {
            uint32_t ah[4], al[4];
            split2(sc[2*ks][0],   sc[2*ks][1],   ah[0], al[0]);
            split2(sc[2*ks][2],   sc[2*ks][3],   ah[1], al[1]);
            split2(sc[2*ks+1][0], sc[2*ks+1][1], ah[2], al[2]);
            split2(sc[2*ks+1][2], sc[2*ks+1][3], ah[3], al[3]);
            #pragma unroll
            for (int j = 0; j < 4; j++) {
                uint32_t addr = st + 2 * AK_MAT + (uint32_t)((ks * 16 + vrow) * AT_RS) + j * 32 + vcol;
                uint32_t vh4[4], vl4[4];
                ldsm4t(vh4, addr);
                ldsm4t(vl4, addr + AK_MAT);
                #pragma unroll
                for (int jj = 0; jj < 2; jj++) {
                    int t = j * 2 + jj;
                    mma_bf16(o[t], ah, &vh4[jj * 2]);
                    mma_bf16(o[t], ah, &vl4[jj * 2]);
                    mma_bf16(o[t], al, &vh4[jj * 2]);
                }
            }
        }
        __syncthreads();
    }

    // ---- epilogue: y = O / l -> bf16 hi/lo (EMB stride) ----
    const float inv0 = 1.0f / l0, inv1 = 1.0f / l1;
    const int tok0 = b * SEQ + qt * 128 + warp * 16 + (lane >> 2);
    #pragma unroll
    for (int t = 0; t < 8; t++) {
        int col = t * 8 + (lane & 3) * 2;
        size_t i0 = (size_t)tok0 * EMB + hoff + col;
        size_t i1 = i0 + (size_t)8 * EMB;
        uint32_t h0, lo0, h1, lo1;
        split2(o[t][0] * inv0, o[t][1] * inv0, h0, lo0);
        split2(o[t][2] * inv1, o[t][3] * inv1, h1, lo1);
        *(uint32_t*)(Yh + i0) = h0;
        *(uint32_t*)(Yl + i0) = lo0;
        *(uint32_t*)(Yh + i1) = h1;
        *(uint32_t*)(Yl + i1) = lo1;
    }
}

// ------------------------------- launch -------------------------------------
extern "C" void kernel_launch(void* const* d_in, const int* in_sizes, int n_in,
                              void* d_out, int out_size)
{
    const float* x     = (const float*)d_in[0];
    const float* Wq    = (const float*)d_in[1];
    const float* bq    = (const float*)d_in[2];
    const float* Wk    = (const float*)d_in[3];
    const float* bk    = (const float*)d_in[4];
    const float* Wv    = (const float*)d_in[5];
    const float* bv    = (const float*)d_in[6];
    const float* Wo    = (const float*)d_in[7];
    const float* bo    = (const float*)d_in[8];
    const float* g1    = (const float*)d_in[9];
    const float* beta1 = (const float*)d_in[10];
    const float* g2    = (const float*)d_in[11];
    const float* beta2 = (const float*)d_in[12];
    const float* W1    = (const float*)d_in[13];
    const float* b1    = (const float*)d_in[14];
    const float* W2    = (const float*)d_in[15];
    const float* b2    = (const float*)d_in[16];
    float* out = (float*)d_out;

    __nv_bfloat16 *qkvh, *qkvl, *hh, *hl, *yh, *yl, *fh, *fl;
    __nv_bfloat16 *wqkvh, *wqkvl, *woh, *wol, *w1h, *w1l, *w2h, *w2l;
    cudaGetSymbolAddress((void**)&qkvh, s_qkvh); cudaGetSymbolAddress((void**)&qkvl, s_qkvl);
    cudaGetSymbolAddress((void**)&hh, s_hh);     cudaGetSymbolAddress((void**)&hl, s_hl);
    cudaGetSymbolAddress((void**)&yh, s_yh);     cudaGetSymbolAddress((void**)&yl, s_yl);
    cudaGetSymbolAddress((void**)&fh, s_fh);     cudaGetSymbolAddress((void**)&fl, s_fl);
    cudaGetSymbolAddress((void**)&wqkvh, w_qkvh); cudaGetSymbolAddress((void**)&wqkvl, w_qkvl);
    cudaGetSymbolAddress((void**)&woh, w_oh);    cudaGetSymbolAddress((void**)&wol, w_ol);
    cudaGetSymbolAddress((void**)&w1h, w_1h);    cudaGetSymbolAddress((void**)&w1l, w_1l);
    cudaGetSymbolAddress((void**)&w2h, w_2h);    cudaGetSymbolAddress((void**)&w2l, w_2l);

    cudaFuncSetAttribute(gemm_mma, cudaFuncAttributeMaxDynamicSharedMemorySize, SMEM_TOTAL);
    cudaFuncSetAttribute(attn_mma, cudaFuncAttributeMaxDynamicSharedMemorySize, AT_SMEM);

    dim3 tb(32, 8);
    // launch #0, #1: batched weight prepasses
    wprep_attn<<<dim3(32, 32, 4), tb>>>(Wq, Wk, Wv, Wo, wqkvh, wqkvl, woh, wol);
    wprep_mlp<<<dim3(128, 128, 2), tb>>>(W1, W2, w1h, w1l, w2h, w2l);

    dim3 gQKV(QKVN/128, MTOK/128);
    dim3 gE(EMB/128, MTOK/128);
    dim3 gF(FFD/128, MTOK/128);

    // #2: h = LN1(x)
    ln_kernel<<<MTOK, 256>>>(x, g1, beta1, hh, hl);
    // #3: fused qkv = h @ Wqkv + b
    gemm_mma<<<gQKV, 256, SMEM_TOTAL>>>(hh, hl, wqkvh, wqkvl, bq, bk, bv, nullptr,
                                        nullptr, qkvh, qkvl, MTOK, QKVN, EMB, 3);
    // #4: attention -> y hi/lo
    attn_mma<<<dim3(SEQ/128, BSZ*NH), 256, AT_SMEM>>>(qkvh, qkvl, yh, yl);
    // #5 (ncu capture target): x2 = x + y@Wo + bo
    gemm_mma<<<gE, 256, SMEM_TOTAL>>>(yh, yl, woh, wol, bo, nullptr, nullptr, x,
                                      out, nullptr, nullptr, MTOK, EMB, EMB, 2);
    // #6: h2 = LN2(x2)
    ln_kernel<<<MTOK, 256>>>(out, g2, beta2, hh, hl);
    // #7: ff = gelu(h2@W1 + b1)
    gemm_mma<<<gF, 256, SMEM_TOTAL>>>(hh, hl, w1h, w1l, b1, nullptr, nullptr, nullptr,
                                      nullptr, fh, fl, MTOK, FFD, EMB, 1);
    // #8: out = x2 + ff@W2 + b2  (resid = out — fixed null-resid bug)
    gemm_mma<<<gE, 256, SMEM_TOTAL>>>(fh, fl, w2h, w2l, b2, nullptr, nullptr, out,
                                      out, nullptr, nullptr, MTOK, EMB, FFD, 2);
}

// round 16
// speedup vs baseline: 1.0616x; 1.0616x over previous
#include <cuda_runtime.h>
#include <cuda_bf16.h>
#include <math.h>
#include <stdint.h>

#define BSZ 4
#define SEQ 2048
#define EMB 1024
#define NH 16
#define HD 64
#define FFD 4096
#define MTOK 8192   // BSZ*SEQ
#define QKVN 3072   // fused q|k|v output width

// ---------------- scratch (static device arrays, allocation-free) ----------
__device__ __nv_bfloat16 s_qkvh[MTOK*QKVN], s_qkvl[MTOK*QKVN];  // fused QKV out
__device__ __nv_bfloat16 s_hh[MTOK*EMB], s_hl[MTOK*EMB];   // LN out hi/lo
__device__ __nv_bfloat16 s_yh[MTOK*EMB], s_yl[MTOK*EMB];   // attn out hi/lo
__device__ __nv_bfloat16 s_fh[MTOK*FFD], s_fl[MTOK*FFD];   // gelu out hi/lo
// transposed weights [N,K] hi/lo
__device__ __nv_bfloat16 w_qkvh[QKVN*EMB], w_qkvl[QKVN*EMB];   // q|k|v stacked
__device__ __nv_bfloat16 w_oh[EMB*EMB], w_ol[EMB*EMB];
__device__ __nv_bfloat16 w_1h[FFD*EMB], w_1l[FFD*EMB];
__device__ __nv_bfloat16 w_2h[EMB*FFD], w_2l[EMB*FFD];

// --------------------------- PTX helpers ------------------------------------
__device__ __forceinline__ uint32_t smem_u32(const void* p) {
    return (uint32_t)__cvta_generic_to_shared(p);
}
__device__ __forceinline__ void cp16(uint32_t dst, const void* src) {
    asm volatile("cp.async.ca.shared.global [%0], [%1], 16;" :: "r"(dst), "l"(src));
}
#define CP_COMMIT() asm volatile("cp.async.commit_group;" ::: "memory")
#define CP_WAIT1()  asm volatile("cp.async.wait_group 1;" ::: "memory")
#define CP_WAIT0()  asm volatile("cp.async.wait_group 0;" ::: "memory")

__device__ __forceinline__ void ldsm4(uint32_t* r, uint32_t addr) {
    asm volatile("ldmatrix.sync.aligned.m8n8.x4.shared.b16 {%0,%1,%2,%3}, [%4];"
        : "=r"(r[0]), "=r"(r[1]), "=r"(r[2]), "=r"(r[3]) : "r"(addr));
}
__device__ __forceinline__ void ldsm4t(uint32_t* r, uint32_t addr) {
    asm volatile("ldmatrix.sync.aligned.m8n8.x4.trans.shared.b16 {%0,%1,%2,%3}, [%4];"
        : "=r"(r[0]), "=r"(r[1]), "=r"(r[2]), "=r"(r[3]) : "r"(addr));
}
__device__ __forceinline__ void mma_bf16(float* d, const uint32_t* a, const uint32_t* b) {
    asm volatile("mma.sync.aligned.m16n8k16.row.col.f32.bf16.bf16.f32 "
        "{%0,%1,%2,%3}, {%4,%5,%6,%7}, {%8,%9}, {%0,%1,%2,%3};"
        : "+f"(d[0]), "+f"(d[1]), "+f"(d[2]), "+f"(d[3])
        : "r"(a[0]), "r"(a[1]), "r"(a[2]), "r"(a[3]), "r"(b[0]), "r"(b[1]));
}
// split two fp32 into packed bf16x2 hi and lo
__device__ __forceinline__ void split2(float x, float y, uint32_t& hi, uint32_t& lo) {
    __nv_bfloat16 hx = __float2bfloat16(x), hy = __float2bfloat16(y);
    __nv_bfloat162 H(hx, hy);
    __nv_bfloat162 L(__float2bfloat16(x - __bfloat162float(hx)),
                     __float2bfloat16(y - __bfloat162float(hy)));
    hi = *(uint32_t*)&H; lo = *(uint32_t*)&L;
}

// ---------------- weight prepass (batched): transpose + split ----------------
__device__ __forceinline__ void wprep_tile(
    const float* __restrict__ W, __nv_bfloat16* __restrict__ Th,
    __nv_bfloat16* __restrict__ Tl, int K, int N, int n0, int k0,
    int tx, int ty, float (*t)[33])
{
    #pragma unroll
    for (int j = 0; j < 4; j++)
        t[ty + 8*j][tx] = W[(size_t)(k0 + ty + 8*j) * N + n0 + tx];
    __syncthreads();
    #pragma unroll
    for (int j = 0; j < 4; j++) {
        int n = n0 + ty + 8*j, k = k0 + tx;
        float v = t[tx][ty + 8*j];
        __nv_bfloat16 h = __float2bfloat16(v);
        Th[(size_t)n * K + k] = h;
        Tl[(size_t)n * K + k] = __float2bfloat16(v - __bfloat162float(h));
    }
}

// batch 1: Wq, Wk, Wv (stacked into w_qkv), Wo.  grid (32, 32, 4), block (32,8)
__global__ void wprep_attn(
    const float* __restrict__ Wq, const float* __restrict__ Wk,
    const float* __restrict__ Wv, const float* __restrict__ Wo,
    __nv_bfloat16* __restrict__ qkvh, __nv_bfloat16* __restrict__ qkvl,
    __nv_bfloat16* __restrict__ oh, __nv_bfloat16* __restrict__ ol)
{
    __shared__ float t[32][33];
    int z = blockIdx.z;
    const float* W = (z == 0) ? Wq : (z == 1) ? Wk : (z == 2) ? Wv : Wo;
    __nv_bfloat16* Th = (z == 3) ? oh : qkvh + (size_t)z * EMB * EMB;
    __nv_bfloat16* Tl = (z == 3) ? ol : qkvl + (size_t)z * EMB * EMB;
    wprep_tile(W, Th, Tl, EMB, EMB, blockIdx.x * 32, blockIdx.y * 32,
               threadIdx.x, threadIdx.y, t);
}

// batch 2: W1 (K=EMB,N=FFD), W2 (K=FFD,N=EMB). grid (128, 128, 2), guarded.
__global__ void wprep_mlp(
    const float* __restrict__ W1, const float* __restrict__ W2,
    __nv_bfloat16* __restrict__ w1h, __nv_bfloat16* __restrict__ w1l,
    __nv_bfloat16* __restrict__ w2h, __nv_bfloat16* __restrict__ w2l)
{
    __shared__ float t[32][33];
    int z = blockIdx.z;
    const float* W = z ? W2 : W1;
    __nv_bfloat16* Th = z ? w2h : w1h;
    __nv_bfloat16* Tl = z ? w2l : w1l;
    int K = z ? FFD : EMB, N = z ? EMB : FFD;
    int n0 = blockIdx.x * 32, k0 = blockIdx.y * 32;
    if (n0 >= N || k0 >= K) return;
    wprep_tile(W, Th, Tl, K, N, n0, k0, threadIdx.x, threadIdx.y, t);
}

// ---------------------------- LayerNorm (bf16 hi/lo out) --------------------
__global__ __launch_bounds__(256) void ln_kernel(
    const float* __restrict__ x, const float* __restrict__ g,
    const float* __restrict__ bta, __nv_bfloat16* __restrict__ oh,
    __nv_bfloat16* __restrict__ ol)
{
    int row = blockIdx.x;
    int t = threadIdx.x;
    const float4* xr = (const float4*)(x + (size_t)row * EMB);
    float4 v = xr[t];
    float s  = v.x + v.y + v.z + v.w;
    float ss = v.x*v.x + v.y*v.y + v.z*v.z + v.w*v.w;
    #pragma unroll
    for (int o = 16; o; o >>= 1) {
        s  += __shfl_xor_sync(0xFFFFFFFFu, s,  o);
        ss += __shfl_xor_sync(0xFFFFFFFFu, ss, o);
    }
    __shared__ float sh_s[8], sh_ss[8];
    __shared__ float s_mu, s_rstd;
    int w = t >> 5;
    if ((t & 31) == 0) { sh_s[w] = s; sh_ss[w] = ss; }
    __syncthreads();
    if (t == 0) {
        float S = 0.f, SS = 0.f;
        #pragma unroll
        for (int i = 0; i < 8; i++) { S += sh_s[i]; SS += sh_ss[i]; }
        float mu  = S * (1.0f / EMB);
        float var = SS * (1.0f / EMB) - mu * mu;
        s_mu = mu; s_rstd = rsqrtf(var + 1e-5f);
    }
    __syncthreads();
    float mu = s_mu, rs = s_rstd;
    float4 gv = ((const float4*)g)[t];
    float4 bv = ((const float4*)bta)[t];
    float o[4];
    o[0] = (v.x - mu) * rs * gv.x + bv.x;
    o[1] = (v.y - mu) * rs * gv.y + bv.y;
    o[2] = (v.z - mu) * rs * gv.z + bv.z;
    o[3] = (v.w - mu) * rs * gv.w + bv.w;
    size_t base = (size_t)row * EMB + t * 4;
    #pragma unroll
    for (int i = 0; i < 4; i++) {
        __nv_bfloat16 h = __float2bfloat16(o[i]);
        oh[base + i] = h;
        ol[base + i] = __float2bfloat16(o[i] - __bfloat162float(h));
    }
}

// ----------------------- mma.sync GEMM (bf16x3 split) ------------------------
// mode 0: C = D+bias   mode 2: C = D+bias+resid
// mode 1: gelu(D+bias) -> (Oh,Ol)    mode 3: D+bias -> (Oh,Ol)
// bias2/bias3: optional per-1024-column-segment biases (fused QKV)
// __launch_bounds__(256,2): cap regs at 128 so 2 CTAs/SM are resident
// (R13 ncu: regs=139 -> 1 CTA/SM, occ 12.4%, tensor 53.9%).
#define RSTRIDE 80
#define MAT_BYTES (128 * RSTRIDE)
#define STAGE_BYTES (4 * MAT_BYTES)
#define SMEM_TOTAL (2 * STAGE_BYTES)

__global__ __launch_bounds__(256, 2) void gemm_mma(
    const __nv_bfloat16* __restrict__ Ah, const __nv_bfloat16* __restrict__ Al,
    const __nv_bfloat16* __restrict__ Bh, const __nv_bfloat16* __restrict__ Bl,
    const float* __restrict__ bias, const float* __restrict__ bias2,
    const float* __restrict__ bias3, const float* __restrict__ resid,
    float* __restrict__ C, __nv_bfloat16* __restrict__ Oh,
    __nv_bfloat16* __restrict__ Ol, int M, int N, int K, int mode)
{
    extern __shared__ char smem[];
    const uint32_t sb = smem_u32(smem);
    const int tid = threadIdx.x;
    const int lane = tid & 31, warp = tid >> 5;
    const int wm = warp & 1, wn = warp >> 1;
    const int bn = blockIdx.x * 128, bm = blockIdx.y * 128;
    const int nch = K >> 5;

    // ---- loader: row = tid>>2 (0..63, +64 for second row), 16B chunk = tid&3
    const int rowA = tid >> 2, ch = tid & 3;
    const char* pA = (const char*)(Ah + (size_t)(bm + rowA) * K + ch * 8);
    const char* pB = (const char*)(Bh + (size_t)(bn + rowA) * K + ch * 8);
    const ptrdiff_t dAlo = (const char*)Al - (const char*)Ah;
    const ptrdiff_t dBlo = (const char*)Bl - (const char*)Bh;
    const size_t rskip = (size_t)128 * K;     // 64 rows * K elems * 2B
    const uint32_t sd0 = sb + rowA * RSTRIDE + ch * 16;

    float acc[4][4][4];
    #pragma unroll
    for (int i = 0; i < 4; i++)
        #pragma unroll
        for (int j = 0; j < 4; j++)
            #pragma unroll
            for (int e = 0; e < 4; e++) acc[i][j][e] = 0.f;

    // prologue: chunk 0 into stage 0
    cp16(sd0,                              pA);
    cp16(sd0 + 64*RSTRIDE,                 pA + rskip);
    cp16(sd0 + MAT_BYTES,                  pA + dAlo);
    cp16(sd0 + MAT_BYTES + 64*RSTRIDE,     pA + dAlo + rskip);
    cp16(sd0 + 2*MAT_BYTES,                pB);
    cp16(sd0 + 2*MAT_BYTES + 64*RSTRIDE,   pB + rskip);
    cp16(sd0 + 3*MAT_BYTES,                pB + dBlo);
    cp16(sd0 + 3*MAT_BYTES + 64*RSTRIDE,   pB + dBlo + rskip);
    CP_COMMIT();

    const int g = lane >> 3, r = lane & 7;
    const uint32_t a_lane = (uint32_t)((wm * 64 + (g & 1) * 8 + r) * RSTRIDE + (g >> 1) * 16);
    const uint32_t b_lane = (uint32_t)((wn * 32 + (g >> 1) * 8 + r) * RSTRIDE + (g & 1) * 16);

    for (int c = 0; c < nch; c++) {
        const int s = c & 1;
        if (c + 1 < nch) {
            const char* a = pA + (size_t)(c + 1) * 64;
            const char* b = pB + (size_t)(c + 1) * 64;
            const uint32_t sd = sd0 + ((c + 1) & 1) * STAGE_BYTES;
            cp16(sd,                              a);
            cp16(sd + 64*RSTRIDE,                 a + rskip);
            cp16(sd + MAT_BYTES,                  a + dAlo);
            cp16(sd + MAT_BYTES + 64*RSTRIDE,     a + dAlo + rskip);
            cp16(sd + 2*MAT_BYTES,                b);
            cp16(sd + 2*MAT_BYTES + 64*RSTRIDE,   b + rskip);
            cp16(sd + 3*MAT_BYTES,                b + dBlo);
            cp16(sd + 3*MAT_BYTES + 64*RSTRIDE,   b + dBlo + rskip);
            CP_COMMIT();
            CP_WAIT1();
        } else {
            CP_WAIT0();
        }
        __syncthreads();

        const uint32_t st = sb + s * STAGE_BYTES;
        #pragma unroll
        for (int kk = 0; kk < 2; kk++) {
            uint32_t bh[2][4], bl[2][4];
            #pragma unroll
            for (int j = 0; j < 2; j++) {
                uint32_t baddr = st + b_lane + j * (16 * RSTRIDE) + kk * 32;
                ldsm4(bh[j], baddr + 2 * MAT_BYTES);
                ldsm4(bl[j], baddr + 3 * MAT_BYTES);
            }
            #pragma unroll
            for (int i = 0; i < 4; i++) {
                uint32_t ah[4], al[4];
                uint32_t aaddr = st + a_lane + i * (16 * RSTRIDE) + kk * 32;
                ldsm4(ah, aaddr);
                ldsm4(al, aaddr + MAT_BYTES);
                #pragma unroll
                for (int jj = 0; jj < 4; jj++) {
                    const uint32_t* Bh2 = &bh[jj >> 1][(jj & 1) * 2];
                    const uint32_t* Bl2 = &bl[jj >> 1][(jj & 1) * 2];
                    mma_bf16(acc[i][jj], ah, Bh2);
                    mma_bf16(acc[i][jj], ah, Bl2);
                    mma_bf16(acc[i][jj], al, Bh2);
                }
            }
        }
        __syncthreads();
    }

    // per-segment bias select (fused QKV): each 128-col CTA tile sits in one segment
    const float* bptr = bias;
    if (bias2) {
        int seg = bn >> 10;
        if (seg == 1) bptr = bias2 - 1024;
        else if (seg == 2) bptr = bias3 - 2048;
    }

    const int rb = bm + wm * 64 + (lane >> 2);
    const int cb = bn + wn * 32 + 2 * (lane & 3);
    #pragma unroll
    for (int i = 0; i < 4; i++) {
        #pragma unroll
        for (int j = 0; j < 4; j++) {
            int row0 = rb + i * 16;
            int col  = cb + j * 8;
            float b0 = __ldg(&bptr[col]), b1 = __ldg(&bptr[col + 1]);
            float v00 = acc[i][j][0] + b0, v01 = acc[i][j][1] + b1;
            float v10 = acc[i][j][2] + b0, v11 = acc[i][j][3] + b1;
            size_t i0 = (size_t)row0 * N + col;
            size_t i1 = (size_t)(row0 + 8) * N + col;
            if (mode == 1 || mode == 3) {
                if (mode == 1) {
                    v00 = 0.5f * v00 * (1.0f + erff(v00 * 0.70710678118654752f));
                    v01 = 0.5f * v01 * (1.0f + erff(v01 * 0.70710678118654752f));
                    v10 = 0.5f * v10 * (1.0f + erff(v10 * 0.70710678118654752f));
                    v11 = 0.5f * v11 * (1.0f + erff(v11 * 0.70710678118654752f));
                }
                uint32_t h0, l0, h1, l1;
                split2(v00, v01, h0, l0);
                split2(v10, v11, h1, l1);
                *(uint32_t*)(Oh + i0) = h0;
                *(uint32_t*)(Oh + i1) = h1;
                *(uint32_t*)(Ol + i0) = l0;
                *(uint32_t*)(Ol + i1) = l1;
            } else {
                if (mode == 2) {
                    float2 r0 = *(const float2*)(resid + i0);
                    float2 r1 = *(const float2*)(resid + i1);
                    v00 += r0.x; v01 += r0.y; v10 += r1.x; v11 += r1.y;
                }
                *(float2*)(C + i0) = make_float2(v00, v01);
                *(float2*)(C + i1) = make_float2(v10, v11);
            }
        }
    }
}

// ----------------- tensor-core flash attention (bf16x3 split) ---------------
// CTA: 128 q-rows, 8 warps (each m16), 64-key tiles, 2-stage cp.async.
// Q/K/V read from fused QKV buffer (row stride QKVN).
#define AT_RS 144
#define AQ_MAT (128 * AT_RS)            // 18432
#define AK_MAT (64 * AT_RS)             // 9216
#define AT_QB (2 * AQ_MAT)              // 36864
#define AT_ST (4 * AK_MAT)              // 36864
#define AT_SMEM (AT_QB + 2 * AT_ST)     // 110592

__global__ __launch_bounds__(256, 2) void attn_mma(
    const __nv_bfloat16* __restrict__ QKVh, const __nv_bfloat16* __restrict__ QKVl,
    __nv_bfloat16* __restrict__ Yh, __nv_bfloat16* __restrict__ Yl)
{
    extern __shared__ char sm[];
    const uint32_t sb = smem_u32(sm);
    const int qt = gridDim.x - 1 - blockIdx.x;          // heavy tiles first
    const int bh = blockIdx.y;
    const int b = bh >> 4, h = bh & 15;
    const int tid = threadIdx.x, lane = tid & 31, warp = tid >> 5;
    const size_t hoff = (size_t)h * HD;
    const int qtok = b * SEQ + qt * 128;

    const int rq = tid >> 3;                    // 0..31
    const int chb = (tid & 7) * 16;             // smem byte offset
    const size_t choff = (size_t)(tid & 7) * 8; // gmem dim offset

    const __nv_bfloat16* kv[4] = { QKVh + 1024, QKVl + 1024, QKVh + 2048, QKVl + 2048 };

    // ---- Q staging: 128 rows hi/lo ----
    #pragma unroll
    for (int mat = 0; mat < 2; mat++) {
        const __nv_bfloat16* base = mat ? QKVl : QKVh;
        #pragma unroll
        for (int rr = 0; rr < 4; rr++) {
            int row = rq + rr * 32;
            cp16(sb + mat * AQ_MAT + row * AT_RS + chb,
                 base + (size_t)(qtok + row) * QKVN + hoff + choff);
        }
    }
    CP_COMMIT();

    // ---- K/V tile 0 ----
    #pragma unroll
    for (int m = 0; m < 4; m++)
        #pragma unroll
        for (int rr = 0; rr < 2; rr++) {
            int row = rq + rr * 32;
            cp16(sb + AT_QB + m * AK_MAT + row * AT_RS + chb,
                 kv[m] + (size_t)(b * SEQ + row) * QKVN + hoff + choff);
        }
    CP_COMMIT();
    CP_WAIT1();
    __syncthreads();

    // ---- Q fragments (warp rows warp*16..+15) ----
    const int g = lane >> 3, rr8 = lane & 7;
    const uint32_t qlane = (uint32_t)((warp * 16 + (g & 1) * 8 + rr8) * AT_RS + (g >> 1) * 16);
    uint32_t qfh[4][4], qfl[4][4];
    #pragma unroll
    for (int ks = 0; ks < 4; ks++) {
        ldsm4(qfh[ks], sb + qlane + ks * 32);
        ldsm4(qfl[ks], sb + AQ_MAT + qlane + ks * 32);
    }

    const uint32_t klane = (uint32_t)(((g >> 1) * 8 + rr8) * AT_RS + (g & 1) * 16);
    const int vrow = (g & 1) * 8 + rr8;
    const uint32_t vcol = (uint32_t)((g >> 1) * 16);

    float o[8][4];
    #pragma unroll
    for (int t = 0; t < 8; t++)
        #pragma unroll
        for (int e = 0; e < 4; e++) o[t][e] = 0.f;
    float m0 = -INFINITY, m1 = -INFINITY, l0 = 0.f, l1 = 0.f;
    const int rg0 = qt * 128 + warp * 16 + (lane >> 2);
    const int cmax = 2 * qt + 1;

    for (int c = 0; c <= cmax; c++) {
        if (c < cmax) {
            const uint32_t so = sb + AT_QB + ((c + 1) & 1) * AT_ST;
            const int nt = b * SEQ + (c + 1) * 64;
            #pragma unroll
            for (int m = 0; m < 4; m++)
                #pragma unroll
                for (int rr = 0; rr < 2; rr++) {
                    int row = rq + rr * 32;
                    cp16(so + m * AK_MAT + row * AT_RS + chb,
                         kv[m] + (size_t)(nt + row) * QKVN + hoff + choff);
                }
            CP_COMMIT();
            CP_WAIT1();
        } else {
            CP_WAIT0();
        }
        __syncthreads();
        const uint32_t st = sb + AT_QB + (c & 1) * AT_ST;

        // ---- S = Q K^T ----
        float sc[8][4];
        #pragma unroll
        for (int t = 0; t < 8; t++)
            #pragma unroll
            for (int e = 0; e < 4; e++) sc[t][e] = 0.f;
        #pragma unroll
        for (int kk = 0; kk < 4; kk++) {
            #pragma unroll
            for (int j = 0; j < 4; j++) {
                uint32_t addr = st + klane + j * (16 * AT_RS) + kk * 32;
                uint32_t kh4[4], kl4[4];
                ldsm4(kh4, addr);
                ldsm4(kl4, addr + AK_MAT);
                #pragma unroll
                for (int jj = 0; jj < 2; jj++) {
                    int t = j * 2 + jj;
                    mma_bf16(sc[t], qfh[kk], &kh4[jj * 2]);
                    mma_bf16(sc[t], qfh[kk], &kl4[jj * 2]);
                    mma_bf16(sc[t], qfl[kk], &kh4[jj * 2]);
                }
            }
        }

        // ---- scale + causal mask (needed only once tile crosses diagonal) ----
        if (c >= 2 * qt) {
            #pragma unroll
            for (int t = 0; t < 8; t++) {
                int col = c * 64 + t * 8 + (lane & 3) * 2;
                sc[t][0] = (col     <= rg0)     ? sc[t][0] * 0.125f : -1e30f;
                sc[t][1] = (col + 1 <= rg0)     ? sc[t][1] * 0.125f : -1e30f;
                sc[t][2] = (col     <= rg0 + 8) ? sc[t][2] * 0.125f : -1e30f;
                sc[t][3] = (col + 1 <= rg0 + 8) ? sc[t][3] * 0.125f : -1e30f;
            }
        } else {
            #pragma unroll
            for (int t = 0; t < 8; t++)
                #pragma unroll
                for (int e = 0; e < 4; e++) sc[t][e] *= 0.125f;
        }

        // ---- online softmax ----
        float rx0 = -INFINITY, rx1 = -INFINITY;
        #pragma unroll
        for (int t = 0; t < 8; t++) {
            rx0 = fmaxf(rx0, fmaxf(sc[t][0], sc[t][1]));
            rx1 = fmaxf(rx1, fmaxf(sc[t][2], sc[t][3]));
        }
        rx0 = fmaxf(rx0, __shfl_xor_sync(0xFFFFFFFFu, rx0, 1));
        rx0 = fmaxf(rx0, __shfl_xor_sync(0xFFFFFFFFu, rx0, 2));
        rx1 = fmaxf(rx1, __shfl_xor_sync(0xFFFFFFFFu, rx1, 1));
        rx1 = fmaxf(rx1, __shfl_xor_sync(0xFFFFFFFFu, rx1, 2));
        float mn0 = fmaxf(m0, rx0), mn1 = fmaxf(m1, rx1);
        float cr0 = __expf(m0 - mn0), cr1 = __expf(m1 - mn1);
        m0 = mn0; m1 = mn1;
        float s0 = 0.f, s1 = 0.f;
        #pragma unroll
        for (int t = 0; t < 8; t++) {
            sc[t][0] = __expf(sc[t][0] - mn0); s0 += sc[t][0];
            sc[t][1] = __expf(sc[t][1] - mn0); s0 += sc[t][1];
            sc[t][2] = __expf(sc[t][2] - mn1); s1 += sc[t][2];
            sc[t][3] = __expf(sc[t][3] - mn1); s1 += sc[t][3];
        }
        s0 += __shfl_xor_sync(0xFFFFFFFFu, s0, 1);
        s0 += __shfl_xor_sync(0xFFFFFFFFu, s0, 2);
        s1 += __shfl_xor_sync(0xFFFFFFFFu, s1, 1);
        s1 += __shfl_xor_sync(0xFFFFFFFFu, s1, 2);
        l0 = l0 * cr0 + s0;
        l1 = l1 * cr1 + s1;
        #pragma unroll
        for (int t = 0; t < 8; t++) {
            o[t][0] *= cr0; o[t][1] *= cr0; o[t][2] *= cr1; o[t][3] *= cr1;
        }

        // ---- O += P V ----
        #pragma unroll
        for (int ks = 0; ks < 4; ks++) {
            uint32_t ah[4], al[4];
            split2(sc[2*ks][0],   sc[2*ks][1],   ah[0], al[0]);
            split2(sc[2*ks][2],   sc[2*ks][3],   ah[1], al[1]);
            split2(sc[2*ks+1][0], sc[2*ks+1][1], ah[2], al[2]);
            split2(sc[2*ks+1][2], sc[2*ks+1][3], ah[3], al[3]);
            #pragma unroll
            for (int j = 0; j < 4; j++) {
                uint32_t addr = st + 2 * AK_MAT + (uint32_t)((ks * 16 + vrow) * AT_RS) + j * 32 + vcol;
                uint32_t vh4[4], vl4[4];
                ldsm4t(vh4, addr);
                ldsm4t(vl4, addr + AK_MAT);
                #pragma unroll
                for (int jj = 0; jj < 2; jj++) {
                    int t = j * 2 + jj;
                    mma_bf16(o[t], ah, &vh4[jj * 2]);
                    mma_bf16(o[t], ah, &vl4[jj * 2]);
                    mma_bf16(o[t], al, &vh4[jj * 2]);
                }
            }
        }
        __syncthreads();
    }

    // ---- epilogue: y = O / l -> bf16 hi/lo (EMB stride) ----
    const float inv0 = 1.0f / l0, inv1 = 1.0f / l1;
    const int tok0 = b * SEQ + qt * 128 + warp * 16 + (lane >> 2);
    #pragma unroll
    for (int t = 0; t < 8; t++) {
        int col = t * 8 + (lane & 3) * 2;
        size_t i0 = (size_t)tok0 * EMB + hoff + col;
        size_t i1 = i0 + (size_t)8 * EMB;
        uint32_t h0, lo0, h1, lo1;
        split2(o[t][0] * inv0, o[t][1] * inv0, h0, lo0);
        split2(o[t][2] * inv1, o[t][3] * inv1, h1, lo1);
        *(uint32_t*)(Yh + i0) = h0;
        *(uint32_t*)(Yl + i0) = lo0;
        *(uint32_t*)(Yh + i1) = h1;
        *(uint32_t*)(Yl + i1) = lo1;
    }
}

// ------------------------------- launch -------------------------------------
extern "C" void kernel_launch(void* const* d_in, const int* in_sizes, int n_in,
                              void* d_out, int out_size)
{
    const float* x     = (const float*)d_in[0];
    const float* Wq    = (const float*)d_in[1];
    const float* bq    = (const float*)d_in[2];
    const float* Wk    = (const float*)d_in[3];
    const float* bk    = (const float*)d_in[4];
    const float* Wv    = (const float*)d_in[5];
    const float* bv    = (const float*)d_in[6];
    const float* Wo    = (const float*)d_in[7];
    const float* bo    = (const float*)d_in[8];
    const float* g1    = (const float*)d_in[9];
    const float* beta1 = (const float*)d_in[10];
    const float* g2    = (const float*)d_in[11];
    const float* beta2 = (const float*)d_in[12];
    const float* W1    = (const float*)d_in[13];
    const float* b1    = (const float*)d_in[14];
    const float* W2    = (const float*)d_in[15];
    const float* b2    = (const float*)d_in[16];
    float* out = (float*)d_out;

    __nv_bfloat16 *qkvh, *qkvl, *hh, *hl, *yh, *yl, *fh, *fl;
    __nv_bfloat16 *wqkvh, *wqkvl, *woh, *wol, *w1h, *w1l, *w2h, *w2l;
    cudaGetSymbolAddress((void**)&qkvh, s_qkvh); cudaGetSymbolAddress((void**)&qkvl, s_qkvl);
    cudaGetSymbolAddress((void**)&hh, s_hh);     cudaGetSymbolAddress((void**)&hl, s_hl);
    cudaGetSymbolAddress((void**)&yh, s_yh);     cudaGetSymbolAddress((void**)&yl, s_yl);
    cudaGetSymbolAddress((void**)&fh, s_fh);     cudaGetSymbolAddress((void**)&fl, s_fl);
    cudaGetSymbolAddress((void**)&wqkvh, w_qkvh); cudaGetSymbolAddress((void**)&wqkvl, w_qkvl);
    cudaGetSymbolAddress((void**)&woh, w_oh);    cudaGetSymbolAddress((void**)&wol, w_ol);
    cudaGetSymbolAddress((void**)&w1h, w_1h);    cudaGetSymbolAddress((void**)&w1l, w_1l);
    cudaGetSymbolAddress((void**)&w2h, w_2h);    cudaGetSymbolAddress((void**)&w2l, w_2l);

    cudaFuncSetAttribute(gemm_mma, cudaFuncAttributeMaxDynamicSharedMemorySize, SMEM_TOTAL);
    cudaFuncSetAttribute(attn_mma, cudaFuncAttributeMaxDynamicSharedMemorySize, AT_SMEM);

    dim3 tb(32, 8);
    // launch #0, #1: batched weight prepasses
    wprep_attn<<<dim3(32, 32, 4), tb>>>(Wq, Wk, Wv, Wo, wqkvh, wqkvl, woh, wol);
    wprep_mlp<<<dim3(128, 128, 2), tb>>>(W1, W2, w1h, w1l, w2h, w2l);

    dim3 gQKV(QKVN/128, MTOK/128);
    dim3 gE(EMB/128, MTOK/128);
    dim3 gF(FFD/128, MTOK/128);

    // #2: h = LN1(x)
    ln_kernel<<<MTOK, 256>>>(x, g1, beta1, hh, hl);
    // #3: fused qkv = h @ Wqkv + b
    gemm_mma<<<gQKV, 256, SMEM_TOTAL>>>(hh, hl, wqkvh, wqkvl, bq, bk, bv, nullptr,
                                        nullptr, qkvh, qkvl, MTOK, QKVN, EMB, 3);
    // #4: attention -> y hi/lo
    attn_mma<<<dim3(SEQ/128, BSZ*NH), 256, AT_SMEM>>>(qkvh, qkvl, yh, yl);
    // #5 (ncu capture target): x2 = x + y@Wo + bo
    gemm_mma<<<gE, 256, SMEM_TOTAL>>>(yh, yl, woh, wol, bo, nullptr, nullptr, x,
                                      out, nullptr, nullptr, MTOK, EMB, EMB, 2);
    // #6: h2 = LN2(x2)
    ln_kernel<<<MTOK, 256>>>(out, g2, beta2, hh, hl);
    // #7: ff = gelu(h2@W1 + b1)
    gemm_mma<<<gF, 256, SMEM_TOTAL>>>(hh, hl, w1h, w1l, b1, nullptr, nullptr, nullptr,
                                      nullptr, fh, fl, MTOK, FFD, EMB, 1);
    // #8: out = x2 + ff@W2 + b2  (resid = out)
    gemm_mma<<<gE, 256, SMEM_TOTAL>>>(fh, fl, w2h, w2l, b2, nullptr, nullptr, out,
                                      out, nullptr, nullptr, MTOK, EMB, FFD, 2);
}

// round 17
// speedup vs baseline: 1.6051x; 1.5120x over previous
#include <cuda_runtime.h>
#include <cuda_bf16.h>
#include <cuda_fp16.h>
#include <math.h>
#include <stdint.h>

#define BSZ 4
#define SEQ 2048
#define EMB 1024
#define NH 16
#define HD 64
#define FFD 4096
#define MTOK 8192   // BSZ*SEQ
#define QKVN 3072   // fused q|k|v output width

// ---------------- scratch (static device arrays, allocation-free) ----------
__device__ __nv_bfloat16 s_qkvh[MTOK*QKVN], s_qkvl[MTOK*QKVN];  // fused QKV out
__device__ __nv_bfloat16 s_hh[MTOK*EMB], s_hl[MTOK*EMB];   // LN1 out hi/lo
__device__ __nv_bfloat16 s_yh[MTOK*EMB], s_yl[MTOK*EMB];   // attn out hi/lo
__device__ __half s_h16[MTOK*EMB];    // LN2 out (fp16 single)
__device__ __half s_f16[MTOK*FFD];    // gelu out (fp16 single)
// transposed weights [N,K]
__device__ __nv_bfloat16 w_qkvh[QKVN*EMB], w_qkvl[QKVN*EMB];   // q|k|v stacked hi/lo
__device__ __nv_bfloat16 w_oh[EMB*EMB], w_ol[EMB*EMB];
__device__ __half w_1f[FFD*EMB];      // W1^T fp16
__device__ __half w_2f[EMB*FFD];      // W2^T fp16

// --------------------------- PTX helpers ------------------------------------
__device__ __forceinline__ uint32_t smem_u32(const void* p) {
    return (uint32_t)__cvta_generic_to_shared(p);
}
__device__ __forceinline__ void cp16(uint32_t dst, const void* src) {
    asm volatile("cp.async.ca.shared.global [%0], [%1], 16;" :: "r"(dst), "l"(src));
}
#define CP_COMMIT() asm volatile("cp.async.commit_group;" ::: "memory")
#define CP_WAIT1()  asm volatile("cp.async.wait_group 1;" ::: "memory")
#define CP_WAIT0()  asm volatile("cp.async.wait_group 0;" ::: "memory")

__device__ __forceinline__ void ldsm4(uint32_t* r, uint32_t addr) {
    asm volatile("ldmatrix.sync.aligned.m8n8.x4.shared.b16 {%0,%1,%2,%3}, [%4];"
        : "=r"(r[0]), "=r"(r[1]), "=r"(r[2]), "=r"(r[3]) : "r"(addr));
}
__device__ __forceinline__ void ldsm4t(uint32_t* r, uint32_t addr) {
    asm volatile("ldmatrix.sync.aligned.m8n8.x4.trans.shared.b16 {%0,%1,%2,%3}, [%4];"
        : "=r"(r[0]), "=r"(r[1]), "=r"(r[2]), "=r"(r[3]) : "r"(addr));
}
__device__ __forceinline__ void mma_bf16(float* d, const uint32_t* a, const uint32_t* b) {
    asm volatile("mma.sync.aligned.m16n8k16.row.col.f32.bf16.bf16.f32 "
        "{%0,%1,%2,%3}, {%4,%5,%6,%7}, {%8,%9}, {%0,%1,%2,%3};"
        : "+f"(d[0]), "+f"(d[1]), "+f"(d[2]), "+f"(d[3])
        : "r"(a[0]), "r"(a[1]), "r"(a[2]), "r"(a[3]), "r"(b[0]), "r"(b[1]));
}
__device__ __forceinline__ void mma_f16(float* d, const uint32_t* a, const uint32_t* b) {
    asm volatile("mma.sync.aligned.m16n8k16.row.col.f32.f16.f16.f32 "
        "{%0,%1,%2,%3}, {%4,%5,%6,%7}, {%8,%9}, {%0,%1,%2,%3};"
        : "+f"(d[0]), "+f"(d[1]), "+f"(d[2]), "+f"(d[3])
        : "r"(a[0]), "r"(a[1]), "r"(a[2]), "r"(a[3]), "r"(b[0]), "r"(b[1]));
}
// split two fp32 into packed bf16x2 hi and lo
__device__ __forceinline__ void split2(float x, float y, uint32_t& hi, uint32_t& lo) {
    __nv_bfloat16 hx = __float2bfloat16(x), hy = __float2bfloat16(y);
    __nv_bfloat162 H(hx, hy);
    __nv_bfloat162 L(__float2bfloat16(x - __bfloat162float(hx)),
                     __float2bfloat16(y - __bfloat162float(hy)));
    hi = *(uint32_t*)&H; lo = *(uint32_t*)&L;
}

// ---------------- weight prepass (batched): transpose + split ----------------
__device__ __forceinline__ void wprep_tile(
    const float* __restrict__ W, __nv_bfloat16* __restrict__ Th,
    __nv_bfloat16* __restrict__ Tl, int K, int N, int n0, int k0,
    int tx, int ty, float (*t)[33])
{
    #pragma unroll
    for (int j = 0; j < 4; j++)
        t[ty + 8*j][tx] = W[(size_t)(k0 + ty + 8*j) * N + n0 + tx];
    __syncthreads();
    #pragma unroll
    for (int j = 0; j < 4; j++) {
        int n = n0 + ty + 8*j, k = k0 + tx;
        float v = t[tx][ty + 8*j];
        __nv_bfloat16 h = __float2bfloat16(v);
        Th[(size_t)n * K + k] = h;
        Tl[(size_t)n * K + k] = __float2bfloat16(v - __bfloat162float(h));
    }
}
__device__ __forceinline__ void wprep_tile_f16(
    const float* __restrict__ W, __half* __restrict__ T,
    int K, int N, int n0, int k0, int tx, int ty, float (*t)[33])
{
    #pragma unroll
    for (int j = 0; j < 4; j++)
        t[ty + 8*j][tx] = W[(size_t)(k0 + ty + 8*j) * N + n0 + tx];
    __syncthreads();
    #pragma unroll
    for (int j = 0; j < 4; j++) {
        int n = n0 + ty + 8*j, k = k0 + tx;
        T[(size_t)n * K + k] = __float2half(t[tx][ty + 8*j]);
    }
}

// batch 1: Wq, Wk, Wv (stacked into w_qkv), Wo.  grid (32, 32, 4), block (32,8)
__global__ void wprep_attn(
    const float* __restrict__ Wq, const float* __restrict__ Wk,
    const float* __restrict__ Wv, const float* __restrict__ Wo,
    __nv_bfloat16* __restrict__ qkvh, __nv_bfloat16* __restrict__ qkvl,
    __nv_bfloat16* __restrict__ oh, __nv_bfloat16* __restrict__ ol)
{
    __shared__ float t[32][33];
    int z = blockIdx.z;
    const float* W = (z == 0) ? Wq : (z == 1) ? Wk : (z == 2) ? Wv : Wo;
    __nv_bfloat16* Th = (z == 3) ? oh : qkvh + (size_t)z * EMB * EMB;
    __nv_bfloat16* Tl = (z == 3) ? ol : qkvl + (size_t)z * EMB * EMB;
    wprep_tile(W, Th, Tl, EMB, EMB, blockIdx.x * 32, blockIdx.y * 32,
               threadIdx.x, threadIdx.y, t);
}

// batch 2 (fp16): W1 (K=EMB,N=FFD), W2 (K=FFD,N=EMB). grid (128, 128, 2), guarded.
__global__ void wprep_mlp_f16(
    const float* __restrict__ W1, const float* __restrict__ W2,
    __half* __restrict__ w1f, __half* __restrict__ w2f)
{
    __shared__ float t[32][33];
    int z = blockIdx.z;
    const float* W = z ? W2 : W1;
    __half* T = z ? w2f : w1f;
    int K = z ? FFD : EMB, N = z ? EMB : FFD;
    int n0 = blockIdx.x * 32, k0 = blockIdx.y * 32;
    if (n0 >= N || k0 >= K) return;
    wprep_tile_f16(W, T, K, N, n0, k0, threadIdx.x, threadIdx.y, t);
}

// ---------------------------- LayerNorm variants -----------------------------
__global__ __launch_bounds__(256) void ln_kernel(
    const float* __restrict__ x, const float* __restrict__ g,
    const float* __restrict__ bta, __nv_bfloat16* __restrict__ oh,
    __nv_bfloat16* __restrict__ ol)
{
    int row = blockIdx.x;
    int t = threadIdx.x;
    const float4* xr = (const float4*)(x + (size_t)row * EMB);
    float4 v = xr[t];
    float s  = v.x + v.y + v.z + v.w;
    float ss = v.x*v.x + v.y*v.y + v.z*v.z + v.w*v.w;
    #pragma unroll
    for (int o = 16; o; o >>= 1) {
        s  += __shfl_xor_sync(0xFFFFFFFFu, s,  o);
        ss += __shfl_xor_sync(0xFFFFFFFFu, ss, o);
    }
    __shared__ float sh_s[8], sh_ss[8];
    __shared__ float s_mu, s_rstd;
    int w = t >> 5;
    if ((t & 31) == 0) { sh_s[w] = s; sh_ss[w] = ss; }
    __syncthreads();
    if (t == 0) {
        float S = 0.f, SS = 0.f;
        #pragma unroll
        for (int i = 0; i < 8; i++) { S += sh_s[i]; SS += sh_ss[i]; }
        float mu  = S * (1.0f / EMB);
        float var = SS * (1.0f / EMB) - mu * mu;
        s_mu = mu; s_rstd = rsqrtf(var + 1e-5f);
    }
    __syncthreads();
    float mu = s_mu, rs = s_rstd;
    float4 gv = ((const float4*)g)[t];
    float4 bv = ((const float4*)bta)[t];
    float o[4];
    o[0] = (v.x - mu) * rs * gv.x + bv.x;
    o[1] = (v.y - mu) * rs * gv.y + bv.y;
    o[2] = (v.z - mu) * rs * gv.z + bv.z;
    o[3] = (v.w - mu) * rs * gv.w + bv.w;
    size_t base = (size_t)row * EMB + t * 4;
    #pragma unroll
    for (int i = 0; i < 4; i++) {
        __nv_bfloat16 h = __float2bfloat16(o[i]);
        oh[base + i] = h;
        ol[base + i] = __float2bfloat16(o[i] - __bfloat162float(h));
    }
}

__global__ __launch_bounds__(256) void ln_fp16(
    const float* __restrict__ x, const float* __restrict__ g,
    const float* __restrict__ bta, __half* __restrict__ o16)
{
    int row = blockIdx.x;
    int t = threadIdx.x;
    const float4* xr = (const float4*)(x + (size_t)row * EMB);
    float4 v = xr[t];
    float s  = v.x + v.y + v.z + v.w;
    float ss = v.x*v.x + v.y*v.y + v.z*v.z + v.w*v.w;
    #pragma unroll
    for (int o = 16; o; o >>= 1) {
        s  += __shfl_xor_sync(0xFFFFFFFFu, s,  o);
        ss += __shfl_xor_sync(0xFFFFFFFFu, ss, o);
    }
    __shared__ float sh_s[8], sh_ss[8];
    __shared__ float s_mu, s_rstd;
    int w = t >> 5;
    if ((t & 31) == 0) { sh_s[w] = s; sh_ss[w] = ss; }
    __syncthreads();
    if (t == 0) {
        float S = 0.f, SS = 0.f;
        #pragma unroll
        for (int i = 0; i < 8; i++) { S += sh_s[i]; SS += sh_ss[i]; }
        float mu  = S * (1.0f / EMB);
        float var = SS * (1.0f / EMB) - mu * mu;
        s_mu = mu; s_rstd = rsqrtf(var + 1e-5f);
    }
    __syncthreads();
    float mu = s_mu, rs = s_rstd;
    float4 gv = ((const float4*)g)[t];
    float4 bv = ((const float4*)bta)[t];
    size_t base = (size_t)row * EMB + t * 4;
    __half2 p0 = __floats2half2_rn((v.x - mu) * rs * gv.x + bv.x,
                                   (v.y - mu) * rs * gv.y + bv.y);
    __half2 p1 = __floats2half2_rn((v.z - mu) * rs * gv.z + bv.z,
                                   (v.w - mu) * rs * gv.w + bv.w);
    *(__half2*)(o16 + base)     = p0;
    *(__half2*)(o16 + base + 2) = p1;
}

// ----------------------- mma.sync GEMM (bf16x3 split) ------------------------
// mode 2: C = D+bias+resid   mode 3: D+bias -> (Oh,Ol)
// bias2/bias3: optional per-1024-column-segment biases (fused QKV)
#define RSTRIDE 80
#define MAT_BYTES (128 * RSTRIDE)
#define STAGE_BYTES (4 * MAT_BYTES)
#define SMEM_TOTAL (2 * STAGE_BYTES)

__global__ __launch_bounds__(256, 2) void gemm_mma(
    const __nv_bfloat16* __restrict__ Ah, const __nv_bfloat16* __restrict__ Al,
    const __nv_bfloat16* __restrict__ Bh, const __nv_bfloat16* __restrict__ Bl,
    const float* __restrict__ bias, const float* __restrict__ bias2,
    const float* __restrict__ bias3, const float* __restrict__ resid,
    float* __restrict__ C, __nv_bfloat16* __restrict__ Oh,
    __nv_bfloat16* __restrict__ Ol, int M, int N, int K, int mode)
{
    extern __shared__ char smem[];
    const uint32_t sb = smem_u32(smem);
    const int tid = threadIdx.x;
    const int lane = tid & 31, warp = tid >> 5;
    const int wm = warp & 1, wn = warp >> 1;
    const int bn = blockIdx.x * 128, bm = blockIdx.y * 128;
    const int nch = K >> 5;

    const int rowA = tid >> 2, ch = tid & 3;
    const char* pA = (const char*)(Ah + (size_t)(bm + rowA) * K + ch * 8);
    const char* pB = (const char*)(Bh + (size_t)(bn + rowA) * K + ch * 8);
    const ptrdiff_t dAlo = (const char*)Al - (const char*)Ah;
    const ptrdiff_t dBlo = (const char*)Bl - (const char*)Bh;
    const size_t rskip = (size_t)128 * K;
    const uint32_t sd0 = sb + rowA * RSTRIDE + ch * 16;

    float acc[4][4][4];
    #pragma unroll
    for (int i = 0; i < 4; i++)
        #pragma unroll
        for (int j = 0; j < 4; j++)
            #pragma unroll
            for (int e = 0; e < 4; e++) acc[i][j][e] = 0.f;

    cp16(sd0,                              pA);
    cp16(sd0 + 64*RSTRIDE,                 pA + rskip);
    cp16(sd0 + MAT_BYTES,                  pA + dAlo);
    cp16(sd0 + MAT_BYTES + 64*RSTRIDE,     pA + dAlo + rskip);
    cp16(sd0 + 2*MAT_BYTES,                pB);
    cp16(sd0 + 2*MAT_BYTES + 64*RSTRIDE,   pB + rskip);
    cp16(sd0 + 3*MAT_BYTES,                pB + dBlo);
    cp16(sd0 + 3*MAT_BYTES + 64*RSTRIDE,   pB + dBlo + rskip);
    CP_COMMIT();

    const int g = lane >> 3, r = lane & 7;
    const uint32_t a_lane = (uint32_t)((wm * 64 + (g & 1) * 8 + r) * RSTRIDE + (g >> 1) * 16);
    const uint32_t b_lane = (uint32_t)((wn * 32 + (g >> 1) * 8 + r) * RSTRIDE + (g & 1) * 16);

    for (int c = 0; c < nch; c++) {
        const int s = c & 1;
        if (c + 1 < nch) {
            const char* a = pA + (size_t)(c + 1) * 64;
            const char* b = pB + (size_t)(c + 1) * 64;
            const uint32_t sd = sd0 + ((c + 1) & 1) * STAGE_BYTES;
            cp16(sd,                              a);
            cp16(sd + 64*RSTRIDE,                 a + rskip);
            cp16(sd + MAT_BYTES,                  a + dAlo);
            cp16(sd + MAT_BYTES + 64*RSTRIDE,     a + dAlo + rskip);
            cp16(sd + 2*MAT_BYTES,                b);
            cp16(sd + 2*MAT_BYTES + 64*RSTRIDE,   b + rskip);
            cp16(sd + 3*MAT_BYTES,                b + dBlo);
            cp16(sd + 3*MAT_BYTES + 64*RSTRIDE,   b + dBlo + rskip);
            CP_COMMIT();
            CP_WAIT1();
        } else {
            CP_WAIT0();
        }
        __syncthreads();

        const uint32_t st = sb + s * STAGE_BYTES;
        #pragma unroll
        for (int kk = 0; kk < 2; kk++) {
            uint32_t bh[2][4], bl[2][4];
            #pragma unroll
            for (int j = 0; j < 2; j++) {
                uint32_t baddr = st + b_lane + j * (16 * RSTRIDE) + kk * 32;
                ldsm4(bh[j], baddr + 2 * MAT_BYTES);
                ldsm4(bl[j], baddr + 3 * MAT_BYTES);
            }
            #pragma unroll
            for (int i = 0; i < 4; i++) {
                uint32_t ah[4], al[4];
                uint32_t aaddr = st + a_lane + i * (16 * RSTRIDE) + kk * 32;
                ldsm4(ah, aaddr);
                ldsm4(al, aaddr + MAT_BYTES);
                #pragma unroll
                for (int jj = 0; jj < 4; jj++) {
                    const uint32_t* Bh2 = &bh[jj >> 1][(jj & 1) * 2];
                    const uint32_t* Bl2 = &bl[jj >> 1][(jj & 1) * 2];
                    mma_bf16(acc[i][jj], ah, Bh2);
                    mma_bf16(acc[i][jj], ah, Bl2);
                    mma_bf16(acc[i][jj], al, Bh2);
                }
            }
        }
        __syncthreads();
    }

    const float* bptr = bias;
    if (bias2) {
        int seg = bn >> 10;
        if (seg == 1) bptr = bias2 - 1024;
        else if (seg == 2) bptr = bias3 - 2048;
    }

    const int rb = bm + wm * 64 + (lane >> 2);
    const int cb = bn + wn * 32 + 2 * (lane & 3);
    #pragma unroll
    for (int i = 0; i < 4; i++) {
        #pragma unroll
        for (int j = 0; j < 4; j++) {
            int row0 = rb + i * 16;
            int col  = cb + j * 8;
            float b0 = __ldg(&bptr[col]), b1 = __ldg(&bptr[col + 1]);
            float v00 = acc[i][j][0] + b0, v01 = acc[i][j][1] + b1;
            float v10 = acc[i][j][2] + b0, v11 = acc[i][j][3] + b1;
            size_t i0 = (size_t)row0 * N + col;
            size_t i1 = (size_t)(row0 + 8) * N + col;
            if (mode == 3) {
                uint32_t h0, l0, h1, l1;
                split2(v00, v01, h0, l0);
                split2(v10, v11, h1, l1);
                *(uint32_t*)(Oh + i0) = h0;
                *(uint32_t*)(Oh + i1) = h1;
                *(uint32_t*)(Ol + i0) = l0;
                *(uint32_t*)(Ol + i1) = l1;
            } else {
                if (mode == 2) {
                    float2 r0 = *(const float2*)(resid + i0);
                    float2 r1 = *(const float2*)(resid + i1);
                    v00 += r0.x; v01 += r0.y; v10 += r1.x; v11 += r1.y;
                }
                *(float2*)(C + i0) = make_float2(v00, v01);
                *(float2*)(C + i1) = make_float2(v10, v11);
            }
        }
    }
}

// ----------------------- mma.sync GEMM (fp16 single) -------------------------
// MLP-only path: A [M,K] fp16, B [N,K] fp16. K-chunk 64, 2-stage.
// mode 1: gelu(D+bias) -> O (fp16)    mode 2: C = D+bias+resid (fp32)
#define F_RS 144
#define F_MAT (128 * F_RS)        // 18432
#define F_STAGE (2 * F_MAT)       // 36864
#define F_SMEM (2 * F_STAGE)      // 73728

__global__ __launch_bounds__(256, 2) void gemm_fp16(
    const __half* __restrict__ A, const __half* __restrict__ B,
    const float* __restrict__ bias, const float* __restrict__ resid,
    float* __restrict__ C, __half* __restrict__ O,
    int M, int N, int K, int mode)
{
    extern __shared__ char smem[];
    const uint32_t sb = smem_u32(smem);
    const int tid = threadIdx.x;
    const int lane = tid & 31, warp = tid >> 5;
    const int wm = warp & 1, wn = warp >> 1;
    const int bn = blockIdx.x * 128, bm = blockIdx.y * 128;
    const int nch = K >> 6;

    // loader: rowA = tid>>3 (0..31, +32*rr), 16B chunk = tid&7 (128B row = K64)
    const int rowA = tid >> 3, ch = tid & 7;
    const char* pA = (const char*)(A + (size_t)(bm + rowA) * K + ch * 8);
    const char* pB = (const char*)(B + (size_t)(bn + rowA) * K + ch * 8);
    const size_t rskip = (size_t)64 * K;   // 32 rows * K * 2B
    const uint32_t sd0 = sb + rowA * F_RS + ch * 16;

    float acc[4][4][4];
    #pragma unroll
    for (int i = 0; i < 4; i++)
        #pragma unroll
        for (int j = 0; j < 4; j++)
            #pragma unroll
            for (int e = 0; e < 4; e++) acc[i][j][e] = 0.f;

    #pragma unroll
    for (int rr = 0; rr < 4; rr++) {
        cp16(sd0 + rr * (32 * F_RS),         pA + rr * rskip);
        cp16(sd0 + F_MAT + rr * (32 * F_RS), pB + rr * rskip);
    }
    CP_COMMIT();

    const int g = lane >> 3, r = lane & 7;
    const uint32_t a_lane = (uint32_t)((wm * 64 + (g & 1) * 8 + r) * F_RS + (g >> 1) * 16);
    const uint32_t b_lane = (uint32_t)((wn * 32 + (g >> 1) * 8 + r) * F_RS + (g & 1) * 16);

    for (int c = 0; c < nch; c++) {
        const int s = c & 1;
        if (c + 1 < nch) {
            const char* a = pA + (size_t)(c + 1) * 128;
            const char* b = pB + (size_t)(c + 1) * 128;
            const uint32_t sd = sd0 + ((c + 1) & 1) * F_STAGE;
            #pragma unroll
            for (int rr = 0; rr < 4; rr++) {
                cp16(sd + rr * (32 * F_RS),         a + rr * rskip);
                cp16(sd + F_MAT + rr * (32 * F_RS), b + rr * rskip);
            }
            CP_COMMIT();
            CP_WAIT1();
        } else {
            CP_WAIT0();
        }
        __syncthreads();

        const uint32_t st = sb + s * F_STAGE;
        #pragma unroll
        for (int kk = 0; kk < 4; kk++) {
            uint32_t bf[2][4];
            #pragma unroll
            for (int j = 0; j < 2; j++)
                ldsm4(bf[j], st + F_MAT + b_lane + j * (16 * F_RS) + kk * 32);
            #pragma unroll
            for (int i = 0; i < 4; i++) {
                uint32_t af[4];
                ldsm4(af, st + a_lane + i * (16 * F_RS) + kk * 32);
                #pragma unroll
                for (int jj = 0; jj < 4; jj++)
                    mma_f16(acc[i][jj], af, &bf[jj >> 1][(jj & 1) * 2]);
            }
        }
        __syncthreads();
    }

    const int rb = bm + wm * 64 + (lane >> 2);
    const int cb = bn + wn * 32 + 2 * (lane & 3);
    #pragma unroll
    for (int i = 0; i < 4; i++) {
        #pragma unroll
        for (int j = 0; j < 4; j++) {
            int row0 = rb + i * 16;
            int col  = cb + j * 8;
            float b0 = __ldg(&bias[col]), b1 = __ldg(&bias[col + 1]);
            float v00 = acc[i][j][0] + b0, v01 = acc[i][j][1] + b1;
            float v10 = acc[i][j][2] + b0, v11 = acc[i][j][3] + b1;
            size_t i0 = (size_t)row0 * N + col;
            size_t i1 = (size_t)(row0 + 8) * N + col;
            if (mode == 1) {
                v00 = 0.5f * v00 * (1.0f + erff(v00 * 0.70710678118654752f));
                v01 = 0.5f * v01 * (1.0f + erff(v01 * 0.70710678118654752f));
                v10 = 0.5f * v10 * (1.0f + erff(v10 * 0.70710678118654752f));
                v11 = 0.5f * v11 * (1.0f + erff(v11 * 0.70710678118654752f));
                *(__half2*)(O + i0) = __floats2half2_rn(v00, v01);
                *(__half2*)(O + i1) = __floats2half2_rn(v10, v11);
            } else {
                float2 r0 = *(const float2*)(resid + i0);
                float2 r1 = *(const float2*)(resid + i1);
                *(float2*)(C + i0) = make_float2(v00 + r0.x, v01 + r0.y);
                *(float2*)(C + i1) = make_float2(v10 + r1.x, v11 + r1.y);
            }
        }
    }
}

// ----------------- tensor-core flash attention (bf16x3 split) ---------------
#define AT_RS 144
#define AQ_MAT (128 * AT_RS)            // 18432
#define AK_MAT (64 * AT_RS)             // 9216
#define AT_QB (2 * AQ_MAT)              // 36864
#define AT_ST (4 * AK_MAT)              // 36864
#define AT_SMEM (AT_QB + 2 * AT_ST)     // 110592

__global__ __launch_bounds__(256, 2) void attn_mma(
    const __nv_bfloat16* __restrict__ QKVh, const __nv_bfloat16* __restrict__ QKVl,
    __nv_bfloat16* __restrict__ Yh, __nv_bfloat16* __restrict__ Yl)
{
    extern __shared__ char sm[];
    const uint32_t sb = smem_u32(sm);
    const int qt = gridDim.x - 1 - blockIdx.x;          // heavy tiles first
    const int bh = blockIdx.y;
    const int b = bh >> 4, h = bh & 15;
    const int tid = threadIdx.x, lane = tid & 31, warp = tid >> 5;
    const size_t hoff = (size_t)h * HD;
    const int qtok = b * SEQ + qt * 128;

    const int rq = tid >> 3;                    // 0..31
    const int chb = (tid & 7) * 16;             // smem byte offset
    const size_t choff = (size_t)(tid & 7) * 8; // gmem dim offset

    const __nv_bfloat16* kv[4] = { QKVh + 1024, QKVl + 1024, QKVh + 2048, QKVl + 2048 };

    #pragma unroll
    for (int mat = 0; mat < 2; mat++) {
        const __nv_bfloat16* base = mat ? QKVl : QKVh;
        #pragma unroll
        for (int rr = 0; rr < 4; rr++) {
            int row = rq + rr * 32;
            cp16(sb + mat * AQ_MAT + row * AT_RS + chb,
                 base + (size_t)(qtok + row) * QKVN + hoff + choff);
        }
    }
    CP_COMMIT();

    #pragma unroll
    for (int m = 0; m < 4; m++)
        #pragma unroll
        for (int rr = 0; rr < 2; rr++) {
            int row = rq + rr * 32;
            cp16(sb + AT_QB + m * AK_MAT + row * AT_RS + chb,
                 kv[m] + (size_t)(b * SEQ + row) * QKVN + hoff + choff);
        }
    CP_COMMIT();
    CP_WAIT1();
    __syncthreads();

    const int g = lane >> 3, rr8 = lane & 7;
    const uint32_t qlane = (uint32_t)((warp * 16 + (g & 1) * 8 + rr8) * AT_RS + (g >> 1) * 16);
    uint32_t qfh[4][4], qfl[4][4];
    #pragma unroll
    for (int ks = 0; ks < 4; ks++) {
        ldsm4(qfh[ks], sb + qlane + ks * 32);
        ldsm4(qfl[ks], sb + AQ_MAT + qlane + ks * 32);
    }

    const uint32_t klane = (uint32_t)(((g >> 1) * 8 + rr8) * AT_RS + (g & 1) * 16);
    const int vrow = (g & 1) * 8 + rr8;
    const uint32_t vcol = (uint32_t)((g >> 1) * 16);

    float o[8][4];
    #pragma unroll
    for (int t = 0; t < 8; t++)
        #pragma unroll
        for (int e = 0; e < 4; e++) o[t][e] = 0.f;
    float m0 = -INFINITY, m1 = -INFINITY, l0 = 0.f, l1 = 0.f;
    const int rg0 = qt * 128 + warp * 16 + (lane >> 2);
    const int cmax = 2 * qt + 1;

    for (int c = 0; c <= cmax; c++) {
        if (c < cmax) {
            const uint32_t so = sb + AT_QB + ((c + 1) & 1) * AT_ST;
            const int nt = b * SEQ + (c + 1) * 64;
            #pragma unroll
            for (int m = 0; m < 4; m++)
                #pragma unroll
                for (int rr = 0; rr < 2; rr++) {
                    int row = rq + rr * 32;
                    cp16(so + m * AK_MAT + row * AT_RS + chb,
                         kv[m] + (size_t)(nt + row) * QKVN + hoff + choff);
                }
            CP_COMMIT();
            CP_WAIT1();
        } else {
            CP_WAIT0();
        }
        __syncthreads();
        const uint32_t st = sb + AT_QB + (c & 1) * AT_ST;

        float sc[8][4];
        #pragma unroll
        for (int t = 0; t < 8; t++)
            #pragma unroll
            for (int e = 0; e < 4; e++) sc[t][e] = 0.f;
        #pragma unroll
        for (int kk = 0; kk < 4; kk++) {
            #pragma unroll
            for (int j = 0; j < 4; j++) {
                uint32_t addr = st + klane + j * (16 * AT_RS) + kk * 32;
                uint32_t kh4[4], kl4[4];
                ldsm4(kh4, addr);
                ldsm4(kl4, addr + AK_MAT);
                #pragma unroll
                for (int jj = 0; jj < 2; jj++) {
                    int t = j * 2 + jj;
                    mma_bf16(sc[t], qfh[kk], &kh4[jj * 2]);
                    mma_bf16(sc[t], qfh[kk], &kl4[jj * 2]);
                    mma_bf16(sc[t], qfl[kk], &kh4[jj * 2]);
                }
            }
        }

        if (c >= 2 * qt) {
            #pragma unroll
            for (int t = 0; t < 8; t++) {
                int col = c * 64 + t * 8 + (lane & 3) * 2;
                sc[t][0] = (col     <= rg0)     ? sc[t][0] * 0.125f : -1e30f;
                sc[t][1] = (col + 1 <= rg0)     ? sc[t][1] * 0.125f : -1e30f;
                sc[t][2] = (col     <= rg0 + 8) ? sc[t][2] * 0.125f : -1e30f;
                sc[t][3] = (col + 1 <= rg0 + 8) ? sc[t][3] * 0.125f : -1e30f;
            }
        } else {
            #pragma unroll
            for (int t = 0; t < 8; t++)
                #pragma unroll
                for (int e = 0; e < 4; e++) sc[t][e] *= 0.125f;
        }

        float rx0 = -INFINITY, rx1 = -INFINITY;
        #pragma unroll
        for (int t = 0; t < 8; t++) {
            rx0 = fmaxf(rx0, fmaxf(sc[t][0], sc[t][1]));
            rx1 = fmaxf(rx1, fmaxf(sc[t][2], sc[t][3]));
        }
        rx0 = fmaxf(rx0, __shfl_xor_sync(0xFFFFFFFFu, rx0, 1));
        rx0 = fmaxf(rx0, __shfl_xor_sync(0xFFFFFFFFu, rx0, 2));
        rx1 = fmaxf(rx1, __shfl_xor_sync(0xFFFFFFFFu, rx1, 1));
        rx1 = fmaxf(rx1, __shfl_xor_sync(0xFFFFFFFFu, rx1, 2));
        float mn0 = fmaxf(m0, rx0), mn1 = fmaxf(m1, rx1);
        float cr0 = __expf(m0 - mn0), cr1 = __expf(m1 - mn1);
        m0 = mn0; m1 = mn1;
        float s0 = 0.f, s1 = 0.f;
        #pragma unroll
        for (int t = 0; t < 8; t++) {
            sc[t][0] = __expf(sc[t][0] - mn0); s0 += sc[t][0];
            sc[t][1] = __expf(sc[t][1] - mn0); s0 += sc[t][1];
            sc[t][2] = __expf(sc[t][2] - mn1); s1 += sc[t][2];
            sc[t][3] = __expf(sc[t][3] - mn1); s1 += sc[t][3];
        }
        s0 += __shfl_xor_sync(0xFFFFFFFFu, s0, 1);
        s0 += __shfl_xor_sync(0xFFFFFFFFu, s0, 2);
        s1 += __shfl_xor_sync(0xFFFFFFFFu, s1, 1);
        s1 += __shfl_xor_sync(0xFFFFFFFFu, s1, 2);
        l0 = l0 * cr0 + s0;
        l1 = l1 * cr1 + s1;
        #pragma unroll
        for (int t = 0; t < 8; t++) {
            o[t][0] *= cr0; o[t][1] *= cr0; o[t][2] *= cr1; o[t][3] *= cr1;
        }

        #pragma unroll
        for (int ks = 0; ks < 4; ks++) {
            uint32_t ah[4], al[4];
            split2(sc[2*ks][0],   sc[2*ks][1],   ah[0], al[0]);
            split2(sc[2*ks][2],   sc[2*ks][3],   ah[1], al[1]);
            split2(sc[2*ks+1][0], sc[2*ks+1][1], ah[2], al[2]);
            split2(sc[2*ks+1][2], sc[2*ks+1][3], ah[3], al[3]);
            #pragma unroll
            for (int j = 0; j < 4; j++) {
                uint32_t addr = st + 2 * AK_MAT + (uint32_t)((ks * 16 + vrow) * AT_RS) + j * 32 + vcol;
                uint32_t vh4[4], vl4[4];
                ldsm4t(vh4, addr);
                ldsm4t(vl4, addr + AK_MAT);
                #pragma unroll
                for (int jj = 0; jj < 2; jj++) {
                    int t = j * 2 + jj;
                    mma_bf16(o[t], ah, &vh4[jj * 2]);
                    mma_bf16(o[t], ah, &vl4[jj * 2]);
                    mma_bf16(o[t], al, &vh4[jj * 2]);
                }
            }
        }
        __syncthreads();
    }

    const float inv0 = 1.0f / l0, inv1 = 1.0f / l1;
    const int tok0 = b * SEQ + qt * 128 + warp * 16 + (lane >> 2);
    #pragma unroll
    for (int t = 0; t < 8; t++) {
        int col = t * 8 + (lane & 3) * 2;
        size_t i0 = (size_t)tok0 * EMB + hoff + col;
        size_t i1 = i0 + (size_t)8 * EMB;
        uint32_t h0, lo0, h1, lo1;
        split2(o[t][0] * inv0, o[t][1] * inv0, h0, lo0);
        split2(o[t][2] * inv1, o[t][3] * inv1, h1, lo1);
        *(uint32_t*)(Yh + i0) = h0;
        *(uint32_t*)(Yl + i0) = lo0;
        *(uint32_t*)(Yh + i1) = h1;
        *(uint32_t*)(Yl + i1) = lo1;
    }
}

// ------------------------------- launch -------------------------------------
extern "C" void kernel_launch(void* const* d_in, const int* in_sizes, int n_in,
                              void* d_out, int out_size)
{
    const float* x     = (const float*)d_in[0];
    const float* Wq    = (const float*)d_in[1];
    const float* bq    = (const float*)d_in[2];
    const float* Wk    = (const float*)d_in[3];
    const float* bk    = (const float*)d_in[4];
    const float* Wv    = (const float*)d_in[5];
    const float* bv    = (const float*)d_in[6];
    const float* Wo    = (const float*)d_in[7];
    const float* bo    = (const float*)d_in[8];
    const float* g1    = (const float*)d_in[9];
    const float* beta1 = (const float*)d_in[10];
    const float* g2    = (const float*)d_in[11];
    const float* beta2 = (const float*)d_in[12];
    const float* W1    = (const float*)d_in[13];
    const float* b1    = (const float*)d_in[14];
    const float* W2    = (const float*)d_in[15];
    const float* b2    = (const float*)d_in[16];
    float* out = (float*)d_out;

    __nv_bfloat16 *qkvh, *qkvl, *hh, *hl, *yh, *yl;
    __nv_bfloat16 *wqkvh, *wqkvl, *woh, *wol;
    __half *h16, *f16, *w1f, *w2f;
    cudaGetSymbolAddress((void**)&qkvh, s_qkvh); cudaGetSymbolAddress((void**)&qkvl, s_qkvl);
    cudaGetSymbolAddress((void**)&hh, s_hh);     cudaGetSymbolAddress((void**)&hl, s_hl);
    cudaGetSymbolAddress((void**)&yh, s_yh);     cudaGetSymbolAddress((void**)&yl, s_yl);
    cudaGetSymbolAddress((void**)&h16, s_h16);   cudaGetSymbolAddress((void**)&f16, s_f16);
    cudaGetSymbolAddress((void**)&wqkvh, w_qkvh); cudaGetSymbolAddress((void**)&wqkvl, w_qkvl);
    cudaGetSymbolAddress((void**)&woh, w_oh);    cudaGetSymbolAddress((void**)&wol, w_ol);
    cudaGetSymbolAddress((void**)&w1f, w_1f);    cudaGetSymbolAddress((void**)&w2f, w_2f);

    cudaFuncSetAttribute(gemm_mma, cudaFuncAttributeMaxDynamicSharedMemorySize, SMEM_TOTAL);
    cudaFuncSetAttribute(gemm_fp16, cudaFuncAttributeMaxDynamicSharedMemorySize, F_SMEM);
    cudaFuncSetAttribute(attn_mma, cudaFuncAttributeMaxDynamicSharedMemorySize, AT_SMEM);

    dim3 tb(32, 8);
    wprep_attn<<<dim3(32, 32, 4), tb>>>(Wq, Wk, Wv, Wo, wqkvh, wqkvl, woh, wol);
    wprep_mlp_f16<<<dim3(128, 128, 2), tb>>>(W1, W2, w1f, w2f);

    dim3 gQKV(QKVN/128, MTOK/128);
    dim3 gE(EMB/128, MTOK/128);
    dim3 gF(FFD/128, MTOK/128);

    // h = LN1(x)
    ln_kernel<<<MTOK, 256>>>(x, g1, beta1, hh, hl);
    // fused qkv = h @ Wqkv + b  (bf16x3)
    gemm_mma<<<gQKV, 256, SMEM_TOTAL>>>(hh, hl, wqkvh, wqkvl, bq, bk, bv, nullptr,
                                        nullptr, qkvh, qkvl, MTOK, QKVN, EMB, 3);
    // attention -> y hi/lo (bf16x3)
    attn_mma<<<dim3(SEQ/128, BSZ*NH), 256, AT_SMEM>>>(qkvh, qkvl, yh, yl);
    // x2 = x + y@Wo + bo  (bf16x3)
    gemm_mma<<<gE, 256, SMEM_TOTAL>>>(yh, yl, woh, wol, bo, nullptr, nullptr, x,
                                      out, nullptr, nullptr, MTOK, EMB, EMB, 2);
    // h2 = LN2(x2) -> fp16
    ln_fp16<<<MTOK, 256>>>(out, g2, beta2, h16);
    // ff = gelu(h2@W1 + b1)  (fp16 single-term)
    gemm_fp16<<<gF, 256, F_SMEM>>>(h16, w1f, b1, nullptr, nullptr, f16,
                                   MTOK, FFD, EMB, 1);
    // out = x2 + ff@W2 + b2  (fp16 single-term)
    gemm_fp16<<<gE, 256, F_SMEM>>>(f16, w2f, b2, out, out, nullptr,
                                   MTOK, EMB, FFD, 2);
}